// round 10
// baseline (speedup 1.0000x reference)
#include <cuda_runtime.h>
#include <math.h>

#define BB   2
#define HH   96
#define WW   96
#define PIX  (HH*WW)        // 9216
#define CINX 2048
#define CIX  512
#define CQKX 64
#define NCL  19

// ---------------- scratch (static device globals; no allocation) ------------
__device__ float g_A  [BB*CIX*PIX];      // 37.75 MB
__device__ float g_Bf [BB*CIX*PIX];
__device__ float g_V  [BB*CIX*PIX];
__device__ float g_Q  [BB*CQKX*PIX];
__device__ float g_K  [BB*CQKX*PIX];
__device__ float g_Att[BB*PIX*192];

// ---------------- 3x3 conv, CO=512 fixed, tiled implicit GEMM ---------------
// tile: 128 co x (8 rows x 16 cols). 256 threads, micro 8co x 8rows x 1col.
// flags: 1 = accumulate into out, 2 = apply scale/bias, 4 = relu
__global__ void __launch_bounds__(256, 2)
conv3x3_kernel(const float* __restrict__ in, const float* __restrict__ wgt,
               const float* __restrict__ scale, const float* __restrict__ bias,
               float* __restrict__ out, int Cin, int WCin, int coff, int flags)
{
    const int tile_w = blockIdx.x * 16;
    const int tile_h = blockIdx.y * 8;
    const int b      = blockIdx.z >> 2;         // CO/128 = 4
    const int co0    = (blockIdx.z & 3) * 128;

    __shared__ float sIn[8][10][18];            // 1440 f
    __shared__ float sW[128][73];               // padded (72 used)

    const int tid = threadIdx.x;
    const int tx  = tid & 15;                   // output column within tile
    const int ty  = tid >> 4;                   // co group (8 channels)

    float acc[8][8];
#pragma unroll
    for (int i = 0; i < 8; ++i)
#pragma unroll
        for (int r = 0; r < 8; ++r) acc[i][r] = 0.f;

    const float* inb = in + (size_t)b * Cin * PIX;

    for (int ck0 = 0; ck0 < Cin; ck0 += 8) {
        __syncthreads();
        // input patch: 8 cin x 10 rows x 18 cols (zero-padded halo)
        for (int idx = tid; idx < 8*180; idx += 256) {
            int c  = idx / 180, rem = idx % 180;
            int r  = rem / 18,  cc  = rem % 18;
            int gh = tile_h - 1 + r, gw = tile_w - 1 + cc;
            float vv = 0.f;
            if ((unsigned)gh < 96u && (unsigned)gw < 96u)
                vv = inb[(size_t)(ck0 + c) * PIX + gh * 96 + gw];
            sIn[c][r][cc] = vv;
        }
        // weights: 128 co x 8 cin x 9 taps (contiguous per co)
        const float* wp = wgt + ((size_t)co0 * WCin + coff + ck0) * 9;
        for (int idx = tid; idx < 128*72; idx += 256) {
            int i = idx / 72, rem = idx - i * 72;
            sW[i][rem] = wp[(size_t)i * WCin * 9 + rem];
        }
        __syncthreads();

#pragma unroll 2
        for (int j = 0; j < 8; ++j) {
#pragma unroll
            for (int ky = 0; ky < 3; ++ky) {
#pragma unroll
                for (int kx = 0; kx < 3; ++kx) {
                    float iv[8];
#pragma unroll
                    for (int r = 0; r < 8; ++r) iv[r] = sIn[j][r + ky][tx + kx];
#pragma unroll
                    for (int i = 0; i < 8; ++i) {
                        float wv = sW[ty*8 + i][j*9 + ky*3 + kx];
#pragma unroll
                        for (int r = 0; r < 8; ++r)
                            acc[i][r] = fmaf(wv, iv[r], acc[i][r]);
                    }
                }
            }
        }
    }

#pragma unroll
    for (int i = 0; i < 8; ++i) {
        int co = co0 + ty*8 + i;
        float s = 1.f, bs = 0.f;
        if (flags & 2) { s = scale[co]; bs = bias[co]; }
#pragma unroll
        for (int r = 0; r < 8; ++r) {
            size_t oi = (((size_t)b*512 + co)*96 + tile_h + r)*96 + tile_w + tx;
            float vv = acc[i][r];
            if (flags & 1) vv += out[oi];
            vv = vv * s + bs;
            if (flags & 4) vv = fmaxf(vv, 0.f);
            out[oi] = vv;
        }
    }
}

// ---------------- 1x1 projection: out[b,o,p] = sum_c W[o,c] in[b,c,p] -------
__global__ void __launch_bounds__(256)
pw_kernel(const float* __restrict__ in, const float* __restrict__ wgt,
          float* __restrict__ out, int Cin, int CO)
{
    const int px0 = blockIdx.x * 128;
    const int o0  = blockIdx.y * 64;
    const int b   = blockIdx.z;
    __shared__ float sIn[16][128];
    __shared__ float sW[64][17];
    const int tid = threadIdx.x, tx = tid & 15, ty = tid >> 4;
    float acc[4][8];
#pragma unroll
    for (int i = 0; i < 4; ++i)
#pragma unroll
        for (int r = 0; r < 8; ++r) acc[i][r] = 0.f;

    const float* inb = in + (size_t)b * Cin * PIX;
    for (int c0 = 0; c0 < Cin; c0 += 16) {
        __syncthreads();
#pragma unroll
        for (int k = 0; k < 8; ++k) {
            int idx = tid + k*256;
            sIn[idx >> 7][idx & 127] =
                inb[(size_t)(c0 + (idx >> 7)) * PIX + px0 + (idx & 127)];
        }
#pragma unroll
        for (int k = 0; k < 4; ++k) {
            int idx = tid + k*256;
            sW[idx >> 4][idx & 15] =
                wgt[(size_t)(o0 + (idx >> 4)) * Cin + c0 + (idx & 15)];
        }
        __syncthreads();
#pragma unroll
        for (int j = 0; j < 16; ++j) {
            float iv[8];
#pragma unroll
            for (int r = 0; r < 8; ++r) iv[r] = sIn[j][tx + 16*r];
#pragma unroll
            for (int i = 0; i < 4; ++i) {
                float wv = sW[ty*4 + i][j];
#pragma unroll
                for (int r = 0; r < 8; ++r)
                    acc[i][r] = fmaf(wv, iv[r], acc[i][r]);
            }
        }
    }
#pragma unroll
    for (int i = 0; i < 4; ++i)
#pragma unroll
        for (int r = 0; r < 8; ++r)
            out[((size_t)b*CO + o0 + ty*4 + i)*PIX + px0 + tx + 16*r] = acc[i][r];
}

// ---------------- energies --------------------------------------------------
// eH[b,h,w,g] = sum_c q[b,c,h,w] k[b,c,g,w]   (mask g==h -> -inf), block=(w,b)
__global__ void __launch_bounds__(256)
energyH_kernel(const float* __restrict__ q, const float* __restrict__ k,
               float* __restrict__ att)
{
    const int w = blockIdx.x, b = blockIdx.y;
    __shared__ float sQ[32][96], sK[32][96];
    const int tid = threadIdx.x;
    float acc[36];
#pragma unroll
    for (int i = 0; i < 36; ++i) acc[i] = 0.f;

    for (int c0 = 0; c0 < CQKX; c0 += 32) {
        __syncthreads();
        for (int idx = tid; idx < 32*96; idx += 256) {
            int c = idx / 96, p = idx % 96;
            size_t off = (size_t)(b*CQKX + c0 + c) * PIX + p*96 + w;
            sQ[c][p] = q[off];
            sK[c][p] = k[off];
        }
        __syncthreads();
#pragma unroll
        for (int it = 0; it < 36; ++it) {
            int oi = it*256 + tid;
            int h = oi / 96, g = oi % 96;
            float s = acc[it];
#pragma unroll
            for (int c = 0; c < 32; ++c) s = fmaf(sQ[c][h], sK[c][g], s);
            acc[it] = s;
        }
    }
#pragma unroll
    for (int it = 0; it < 36; ++it) {
        int oi = it*256 + tid;
        int h = oi / 96, g = oi % 96;
        float vv = (g == h) ? __int_as_float(0xff800000u) : acc[it];
        att[((size_t)((b*96 + h)*96 + w))*192 + g] = vv;
    }
}

// eW[b,h,w,v] = sum_c q[b,c,h,w] k[b,c,h,v], block=(h,b)
__global__ void __launch_bounds__(256)
energyW_kernel(const float* __restrict__ q, const float* __restrict__ k,
               float* __restrict__ att)
{
    const int h = blockIdx.x, b = blockIdx.y;
    __shared__ float sQ[32][96], sK[32][96];
    const int tid = threadIdx.x;
    float acc[36];
#pragma unroll
    for (int i = 0; i < 36; ++i) acc[i] = 0.f;

    for (int c0 = 0; c0 < CQKX; c0 += 32) {
        __syncthreads();
        for (int idx = tid; idx < 32*96; idx += 256) {
            int c = idx / 96, p = idx % 96;
            size_t off = (size_t)(b*CQKX + c0 + c) * PIX + h*96 + p;
            sQ[c][p] = q[off];
            sK[c][p] = k[off];
        }
        __syncthreads();
#pragma unroll
        for (int it = 0; it < 36; ++it) {
            int oi = it*256 + tid;
            int wc = oi / 96, v2 = oi % 96;
            float s = acc[it];
#pragma unroll
            for (int c = 0; c < 32; ++c) s = fmaf(sQ[c][wc], sK[c][v2], s);
            acc[it] = s;
        }
    }
#pragma unroll
    for (int it = 0; it < 36; ++it) {
        int oi = it*256 + tid;
        int wc = oi / 96, v2 = oi % 96;
        att[((size_t)((b*96 + h)*96 + wc))*192 + 96 + v2] = acc[it];
    }
}

// ---------------- softmax over 192 ------------------------------------------
__global__ void softmax_kernel(float* __restrict__ att)
{
    const int t = threadIdx.x;                   // 192 threads
    const size_t base = (size_t)blockIdx.x * 192;
    float v = att[base + t];
    __shared__ float red[6];

    float m = v;
#pragma unroll
    for (int o = 16; o; o >>= 1) m = fmaxf(m, __shfl_xor_sync(0xffffffffu, m, o));
    if ((t & 31) == 0) red[t >> 5] = m;
    __syncthreads();
    m = fmaxf(fmaxf(fmaxf(red[0], red[1]), fmaxf(red[2], red[3])),
              fmaxf(red[4], red[5]));

    float e = expf(v - m);
    float s = e;
#pragma unroll
    for (int o = 16; o; o >>= 1) s += __shfl_xor_sync(0xffffffffu, s, o);
    __syncthreads();
    if ((t & 31) == 0) red[t >> 5] = s;
    __syncthreads();
    s = red[0] + red[1] + red[2] + red[3] + red[4] + red[5];
    att[base + t] = e / s;
}

// ---------------- aggregation -----------------------------------------------
// outH: dst[b,c,h,w] = feat + gamma * sum_g v[b,c,g,w] * aH[b,h,w,g], block=(w,b)
__global__ void __launch_bounds__(256)
aggH_kernel(const float* __restrict__ v, const float* __restrict__ att,
            const float* __restrict__ feat, const float* __restrict__ gp,
            float* __restrict__ dst)
{
    const int w = blockIdx.x, b = blockIdx.y;
    const int tid = threadIdx.x;
    __shared__ float sA[96][97];
    __shared__ float sV[16][97];
    const float gm = *gp;

    for (int idx = tid; idx < 96*96; idx += 256) {
        int h = idx / 96, g = idx % 96;
        sA[h][g] = att[((size_t)((b*96 + h)*96 + w))*192 + g];
    }
    const int clg = tid >> 5;      // 0..7 -> channels 2*clg, 2*clg+1
    const int hq  = tid & 31;      // h = hq + 32*r, r<3

    for (int c0 = 0; c0 < CIX; c0 += 16) {
        __syncthreads();
        for (int idx = tid; idx < 16*96; idx += 256) {
            int cl = idx / 96, g = idx % 96;
            sV[cl][g] = v[(size_t)(b*CIX + c0 + cl) * PIX + g*96 + w];
        }
        __syncthreads();
        float a0[3] = {0.f,0.f,0.f}, a1[3] = {0.f,0.f,0.f};
#pragma unroll 4
        for (int g = 0; g < 96; ++g) {
            float v0 = sV[clg*2][g], v1 = sV[clg*2+1][g];
#pragma unroll
            for (int r = 0; r < 3; ++r) {
                float a = sA[hq + 32*r][g];
                a0[r] = fmaf(v0, a, a0[r]);
                a1[r] = fmaf(v1, a, a1[r]);
            }
        }
#pragma unroll
        for (int r = 0; r < 3; ++r) {
            int h = hq + 32*r;
            size_t oi0 = ((size_t)(b*CIX + c0 + clg*2    )*96 + h)*96 + w;
            size_t oi1 = ((size_t)(b*CIX + c0 + clg*2 + 1)*96 + h)*96 + w;
            dst[oi0] = feat[oi0] + gm * a0[r];
            dst[oi1] = feat[oi1] + gm * a1[r];
        }
    }
}

// outW: dst[b,c,h,w] += gamma * sum_v v[b,c,h,v] * aW[b,h,w,v], block=(h,b)
__global__ void __launch_bounds__(256)
aggW_kernel(const float* __restrict__ v, const float* __restrict__ att,
            const float* __restrict__ gp, float* __restrict__ dst)
{
    const int h = blockIdx.x, b = blockIdx.y;
    const int tid = threadIdx.x;
    __shared__ float sA[96][97];
    __shared__ float sV[16][97];
    const float gm = *gp;

    for (int idx = tid; idx < 96*96; idx += 256) {
        int wc = idx / 96, v2 = idx % 96;
        sA[wc][v2] = att[((size_t)((b*96 + h)*96 + wc))*192 + 96 + v2];
    }
    const int clg = tid >> 5;
    const int wq  = tid & 31;

    for (int c0 = 0; c0 < CIX; c0 += 16) {
        __syncthreads();
        for (int idx = tid; idx < 16*96; idx += 256) {
            int cl = idx / 96, v2 = idx % 96;
            sV[cl][v2] = v[(size_t)(b*CIX + c0 + cl) * PIX + h*96 + v2];
        }
        __syncthreads();
        float a0[3] = {0.f,0.f,0.f}, a1[3] = {0.f,0.f,0.f};
#pragma unroll 4
        for (int v2 = 0; v2 < 96; ++v2) {
            float v0 = sV[clg*2][v2], v1 = sV[clg*2+1][v2];
#pragma unroll
            for (int r = 0; r < 3; ++r) {
                float a = sA[wq + 32*r][v2];
                a0[r] = fmaf(v0, a, a0[r]);
                a1[r] = fmaf(v1, a, a1[r]);
            }
        }
#pragma unroll
        for (int r = 0; r < 3; ++r) {
            int wc = wq + 32*r;
            size_t oi0 = ((size_t)(b*CIX + c0 + clg*2    )*96 + h)*96 + wc;
            size_t oi1 = ((size_t)(b*CIX + c0 + clg*2 + 1)*96 + h)*96 + wc;
            dst[oi0] += gm * a0[r];
            dst[oi1] += gm * a1[r];
        }
    }
}

// ---------------- final 1x1 (19 classes) + bias ------------------------------
__global__ void __launch_bounds__(256)
final_kernel(const float* __restrict__ in, const float* __restrict__ ow,
             const float* __restrict__ ob, float* __restrict__ out)
{
    const int px0 = blockIdx.x * 256;
    const int b   = blockIdx.y;
    const int tid = threadIdx.x;
    __shared__ float sIn[32][256];
    __shared__ float sW[19][32];
    float acc[NCL];
#pragma unroll
    for (int o = 0; o < NCL; ++o) acc[o] = 0.f;

    for (int c0 = 0; c0 < CIX; c0 += 32) {
        __syncthreads();
#pragma unroll
        for (int k = 0; k < 32; ++k)
            sIn[k][tid] = in[(size_t)(b*CIX + c0 + k) * PIX + px0 + tid];
        for (int idx = tid; idx < NCL*32; idx += 256)
            sW[idx >> 5][idx & 31] = ow[(size_t)(idx >> 5) * CIX + c0 + (idx & 31)];
        __syncthreads();
#pragma unroll
        for (int j = 0; j < 32; ++j) {
            float xv = sIn[j][tid];
#pragma unroll
            for (int o = 0; o < NCL; ++o) acc[o] = fmaf(sW[o][j], xv, acc[o]);
        }
    }
#pragma unroll
    for (int o = 0; o < NCL; ++o)
        out[((size_t)(b*NCL + o)) * PIX + px0 + tid] = acc[o] + ob[o];
}

// ---------------- launcher ---------------------------------------------------
extern "C" void kernel_launch(void* const* d_in, const int* in_sizes, int n_in,
                              void* d_out, int out_size)
{
    const float* x       = (const float*)d_in[0];
    const float* conva_w = (const float*)d_in[1];
    const float* bn1_s   = (const float*)d_in[2];
    const float* bn1_b   = (const float*)d_in[3];
    const float* q_w     = (const float*)d_in[4];
    const float* k_w     = (const float*)d_in[5];
    const float* v_w     = (const float*)d_in[6];
    const float* gamma   = (const float*)d_in[7];
    const float* convb_w = (const float*)d_in[8];
    const float* bn2_s   = (const float*)d_in[9];
    const float* bn2_b   = (const float*)d_in[10];
    const float* bott_w  = (const float*)d_in[11];
    const float* bn3_s   = (const float*)d_in[12];
    const float* bn3_b   = (const float*)d_in[13];
    const float* out_w   = (const float*)d_in[14];
    const float* out_b   = (const float*)d_in[15];
    float* out = (float*)d_out;

    float *pA, *pB, *pV, *pQ, *pK, *pAtt;
    cudaGetSymbolAddress((void**)&pA,   g_A);
    cudaGetSymbolAddress((void**)&pB,   g_Bf);
    cudaGetSymbolAddress((void**)&pV,   g_V);
    cudaGetSymbolAddress((void**)&pQ,   g_Q);
    cudaGetSymbolAddress((void**)&pK,   g_K);
    cudaGetSymbolAddress((void**)&pAtt, g_Att);

    dim3 cgrid(6, 12, BB * (CIX/128));   // (6,12,8)

    // conva + bn1 + relu -> A
    conv3x3_kernel<<<cgrid, 256>>>(x, conva_w, bn1_s, bn1_b, pA,
                                   CINX, CINX, 0, 2|4);

    // 2 recurrences of criss-cross attention
    for (int r = 0; r < 2; ++r) {
        const float* feat = r ? pB : pA;
        float*       dst  = r ? pA : pB;
        pw_kernel<<<dim3(72, 1, BB), 256>>>(feat, q_w, pQ, CIX, CQKX);
        pw_kernel<<<dim3(72, 1, BB), 256>>>(feat, k_w, pK, CIX, CQKX);
        pw_kernel<<<dim3(72, 8, BB), 256>>>(feat, v_w, pV, CIX, CIX);
        energyH_kernel<<<dim3(96, BB), 256>>>(pQ, pK, pAtt);
        energyW_kernel<<<dim3(96, BB), 256>>>(pQ, pK, pAtt);
        softmax_kernel<<<BB*PIX, 192>>>(pAtt);
        aggH_kernel<<<dim3(96, BB), 256>>>(pV, pAtt, feat, gamma, dst);
        aggW_kernel<<<dim3(96, BB), 256>>>(pV, pAtt, gamma, dst);
    }

    // convb + bn2 + relu : A -> B
    conv3x3_kernel<<<cgrid, 256>>>(pA, convb_w, bn2_s, bn2_b, pB,
                                   CIX, CIX, 0, 2|4);

    // bottleneck conv over virtual concat [x (2048ch), B (512ch)] -> V, bn3
    conv3x3_kernel<<<cgrid, 256>>>(x,  bott_w, nullptr, nullptr, pV,
                                   CINX, CINX + CIX, 0, 0);
    conv3x3_kernel<<<cgrid, 256>>>(pB, bott_w, bn3_s, bn3_b, pV,
                                   CIX, CINX + CIX, CINX, 1|2);

    // final 1x1 -> d_out
    final_kernel<<<dim3(PIX/256, BB), 256>>>(pV, out_w, out_b, out);
}

// round 13
// speedup vs baseline: 1.9610x; 1.9610x over previous
#include <cuda_runtime.h>
#include <cuda_bf16.h>
#include <math.h>
#include <cstdint>

#define BB   2
#define HH   96
#define WW   96
#define PIX  (HH*WW)        // 9216
#define CINX 2048
#define CIX  512
#define CQKX 64
#define NCL  19

// ---------------- scratch (static device globals; no allocation) ------------
__device__ float g_A  [BB*CIX*PIX];
__device__ float g_Bf [BB*CIX*PIX];
__device__ float g_V  [BB*CIX*PIX];
__device__ float g_Q  [BB*CQKX*PIX];
__device__ float g_K  [BB*CQKX*PIX];
__device__ float g_Att[BB*PIX*192];

// ---------------- bf16x2 split helpers ---------------------------------------
// x = hi + lo, hi = bf16(x), lo = bf16(x - hi). Effective precision ~2^-18.
__device__ __forceinline__ void split2(float x0, float x1,
                                       uint32_t& hi, uint32_t& lo) {
    __nv_bfloat16 h0 = __float2bfloat16_rn(x0);
    __nv_bfloat16 h1 = __float2bfloat16_rn(x1);
    __nv_bfloat16 l0 = __float2bfloat16_rn(x0 - __bfloat162float(h0));
    __nv_bfloat16 l1 = __float2bfloat16_rn(x1 - __bfloat162float(h1));
    hi = (uint32_t)__bfloat16_as_ushort(h0)
       | ((uint32_t)__bfloat16_as_ushort(h1) << 16);
    lo = (uint32_t)__bfloat16_as_ushort(l0)
       | ((uint32_t)__bfloat16_as_ushort(l1) << 16);
}

// m16n8k16 bf16 MMA; accumulator layout identical to m16n8k8 tf32.
#define MMA_BF16(d, a, b0, b1)                                                  \
    asm volatile("mma.sync.aligned.m16n8k16.row.col.f32.bf16.bf16.f32 "         \
        "{%0,%1,%2,%3}, {%4,%5,%6,%7}, {%8,%9}, {%0,%1,%2,%3};"                  \
        : "+f"((d)[0]), "+f"((d)[1]), "+f"((d)[2]), "+f"((d)[3])                 \
        : "r"((a)[0]), "r"((a)[1]), "r"((a)[2]), "r"((a)[3]),                    \
          "r"(b0), "r"(b1))

// ============ bf16x2 mma.sync implicit-GEMM 3x3 conv =========================
// block: 128 co x 128 px (8 rows x 16 cols). 256 thr = 8 warps (4 co x 2 px).
// warp tile 32co x 64px. K = Cin*9, chunked by 32 (= 16 bf16 pairs) in
// (cin,tap) order. Each chunk: 2 k16-steps x 3 split products.
// smem rows: 16 used pairs + 4 pad = stride 20 u32 (fragment loads hit all
// 32 banks: (20*g + tig) mod 32 distinct for g=0..7, tig=0..3).
#define PADK      20
#define CSM_PATCH 0                        // 32 x 10 x 18 f32 = 23040
#define CSM_AH    23040                    // 128*20*4 = 10240
#define CSM_AL    (23040 + 10240)
#define CSM_BH    (23040 + 2*10240)
#define CSM_BL    (23040 + 3*10240)
#define CSM_TOTAL (23040 + 4*10240)        // 64000 B

__global__ void __launch_bounds__(256, 2)
conv_tc_kernel(const float* __restrict__ in, const float* __restrict__ wgt,
               const float* __restrict__ scale, const float* __restrict__ bias,
               float* __restrict__ outp, int Cin, int WCin9, int coff9, int flags)
{
    extern __shared__ char smem[];
    float*    sPatch = (float*)(smem + CSM_PATCH);
    uint32_t* sAh    = (uint32_t*)(smem + CSM_AH);
    uint32_t* sAl    = (uint32_t*)(smem + CSM_AL);
    uint32_t* sBh    = (uint32_t*)(smem + CSM_BH);
    uint32_t* sBl    = (uint32_t*)(smem + CSM_BL);

    const int tid  = threadIdx.x;
    const int lane = tid & 31;
    const int wid  = tid >> 5;
    const int g    = lane >> 2;          // group row/col 0..7
    const int tig  = lane & 3;           // thread-in-group 0..3
    const int mw   = (wid & 3) * 32;     // warp co offset
    const int nw   = (wid >> 2) * 64;    // warp px offset

    const int tile_w = blockIdx.x * 16;
    const int tile_h = blockIdx.y * 8;
    const int b      = blockIdx.z >> 2;
    const int co0    = (blockIdx.z & 3) * 128;

    float acc[2][8][4];
#pragma unroll
    for (int mi = 0; mi < 2; ++mi)
#pragma unroll
        for (int ni = 0; ni < 8; ++ni)
#pragma unroll
            for (int q = 0; q < 4; ++q) acc[mi][ni][q] = 0.f;

    const float* inb = in + (size_t)b * Cin * PIX;
    const int groups = Cin >> 5;

    // B-build assignment: px = tid>>1, k-half = (tid&1)*16 -> pairs (tid&1)*8
    const int px_b  = tid >> 1;
    const int kh_b  = (tid & 1) * 16;
    const int kp_b  = (tid & 1) * 8;
    const int rp_b  = px_b >> 4, cp_b = px_b & 15;

    int step = 0;
    for (int grp = 0; grp < groups; ++grp) {
        // ---- stage input patch: 32 cin x 10 x 18 (zero halo) ----
        for (int idx = tid; idx < 32 * 180; idx += 256) {
            int c = idx / 180, rem = idx % 180;
            int pr = rem / 18, pc = rem % 18;
            int gh = tile_h - 1 + pr, gw = tile_w - 1 + pc;
            float v = 0.f;
            if ((unsigned)gh < 96u && (unsigned)gw < 96u)
                v = inb[(size_t)(grp * 32 + c) * PIX + gh * 96 + gw];
            sPatch[idx] = v;
        }

        for (int c9 = 0; c9 < 9; ++c9, ++step) {
            __syncthreads();   // patch ready AND previous chunk's MMAs done

            // ---- stage A: 128co x 32k -> bf16 hi/lo pairs ----
            {
                const float* wb = wgt + coff9 + step * 32;
#pragma unroll
                for (int i = 0; i < 4; ++i) {
                    int idx = tid + i * 256;          // float4 slot 0..1023
                    int co = idx >> 3, j4 = idx & 7;
                    const float4 wv = *(const float4*)(wb +
                        (size_t)(co0 + co) * WCin9 + j4 * 4);
                    uint32_t h0, l0, h1, l1;
                    split2(wv.x, wv.y, h0, l0);
                    split2(wv.z, wv.w, h1, l1);
                    const int d = co * PADK + j4 * 2;
                    sAh[d] = h0; sAh[d + 1] = h1;
                    sAl[d] = l0; sAl[d + 1] = l1;
                }
            }
            // ---- build B: im2col 128px x 32k -> bf16 hi/lo pairs ----
            {
                uint32_t* dh = sBh + px_b * PADK + kp_b;
                uint32_t* dl = sBl + px_b * PADK + kp_b;
#pragma unroll
                for (int jp = 0; jp < 8; ++jp) {
                    int k0 = c9 * 32 + kh_b + 2 * jp;
                    int cl0 = k0 / 9, tp0 = k0 - cl0 * 9;
                    int k1 = k0 + 1;
                    int cl1 = k1 / 9, tp1 = k1 - cl1 * 9;
                    int dy0 = tp0 / 3, dx0 = tp0 - dy0 * 3;
                    int dy1 = tp1 / 3, dx1 = tp1 - dy1 * 3;
                    float v0 = sPatch[cl0 * 180 + (rp_b + dy0) * 18 + (cp_b + dx0)];
                    float v1 = sPatch[cl1 * 180 + (rp_b + dy1) * 18 + (cp_b + dx1)];
                    uint32_t h, l;
                    split2(v0, v1, h, l);
                    dh[jp] = h; dl[jp] = l;
                }
            }
            __syncthreads();   // tiles ready

            // ---- compute: 2 k16-steps x 8 ni x (hi*hi + hi*lo + lo*hi) ----
#pragma unroll
            for (int ks = 0; ks < 2; ++ks) {
                const int kb = ks * 8;
                uint32_t ah[2][4], al[2][4];
#pragma unroll
                for (int mi = 0; mi < 2; ++mi) {
                    const uint32_t* aph = sAh + (mw + mi * 16 + g) * PADK + kb + tig;
                    ah[mi][0] = aph[0];
                    ah[mi][1] = aph[8 * PADK];
                    ah[mi][2] = aph[4];
                    ah[mi][3] = aph[8 * PADK + 4];
                    const uint32_t* apl = sAl + (mw + mi * 16 + g) * PADK + kb + tig;
                    al[mi][0] = apl[0];
                    al[mi][1] = apl[8 * PADK];
                    al[mi][2] = apl[4];
                    al[mi][3] = apl[8 * PADK + 4];
                }
#pragma unroll
                for (int ni = 0; ni < 8; ++ni) {
                    const uint32_t* bph = sBh + (nw + ni * 8 + g) * PADK + kb + tig;
                    uint32_t b0h = bph[0], b1h = bph[4];
                    const uint32_t* bpl = sBl + (nw + ni * 8 + g) * PADK + kb + tig;
                    uint32_t b0l = bpl[0], b1l = bpl[4];
                    MMA_BF16(acc[0][ni], ah[0], b0h, b1h);
                    MMA_BF16(acc[1][ni], ah[1], b0h, b1h);
                    MMA_BF16(acc[0][ni], ah[0], b0l, b1l);
                    MMA_BF16(acc[1][ni], ah[1], b0l, b1l);
                    MMA_BF16(acc[0][ni], al[0], b0h, b1h);
                    MMA_BF16(acc[1][ni], al[1], b0h, b1h);
                }
            }
        }
        __syncthreads();       // guard patch overwrite
    }

    // ---- epilogue: acc -> gmem (bn / relu / accumulate) ----
#pragma unroll
    for (int mi = 0; mi < 2; ++mi) {
#pragma unroll
        for (int rr = 0; rr < 2; ++rr) {
            int co = co0 + mw + mi * 16 + g + rr * 8;
            float s = 1.f, bs = 0.f;
            if (flags & 2) { s = scale[co]; bs = bias[co]; }
            const size_t obase = ((size_t)(b * 512 + co)) * PIX;
#pragma unroll
            for (int ni = 0; ni < 8; ++ni) {
#pragma unroll
                for (int cc = 0; cc < 2; ++cc) {
                    int px = nw + ni * 8 + 2 * tig + cc;
                    size_t oi = obase + (size_t)(tile_h + (px >> 4)) * 96
                              + tile_w + (px & 15);
                    float v = acc[mi][ni][rr * 2 + cc];
                    if (flags & 1) v += outp[oi];
                    v = v * s + bs;
                    if (flags & 4) v = fmaxf(v, 0.f);
                    outp[oi] = v;
                }
            }
        }
    }
}

// ---------------- 1x1 projection (unchanged, proven) -------------------------
__global__ void __launch_bounds__(256)
pw_kernel(const float* __restrict__ in, const float* __restrict__ wgt,
          float* __restrict__ out, int Cin, int CO)
{
    const int px0 = blockIdx.x * 128;
    const int o0  = blockIdx.y * 64;
    const int b   = blockIdx.z;
    __shared__ float sIn[16][128];
    __shared__ float sW[64][17];
    const int tid = threadIdx.x, tx = tid & 15, ty = tid >> 4;
    float acc[4][8];
#pragma unroll
    for (int i = 0; i < 4; ++i)
#pragma unroll
        for (int r = 0; r < 8; ++r) acc[i][r] = 0.f;

    const float* inb = in + (size_t)b * Cin * PIX;
    for (int c0 = 0; c0 < Cin; c0 += 16) {
        __syncthreads();
#pragma unroll
        for (int k = 0; k < 8; ++k) {
            int idx = tid + k*256;
            sIn[idx >> 7][idx & 127] =
                inb[(size_t)(c0 + (idx >> 7)) * PIX + px0 + (idx & 127)];
        }
#pragma unroll
        for (int k = 0; k < 4; ++k) {
            int idx = tid + k*256;
            sW[idx >> 4][idx & 15] =
                wgt[(size_t)(o0 + (idx >> 4)) * Cin + c0 + (idx & 15)];
        }
        __syncthreads();
#pragma unroll
        for (int j = 0; j < 16; ++j) {
            float iv[8];
#pragma unroll
            for (int r = 0; r < 8; ++r) iv[r] = sIn[j][tx + 16*r];
#pragma unroll
            for (int i = 0; i < 4; ++i) {
                float wv = sW[ty*4 + i][j];
#pragma unroll
                for (int r = 0; r < 8; ++r)
                    acc[i][r] = fmaf(wv, iv[r], acc[i][r]);
            }
        }
    }
#pragma unroll
    for (int i = 0; i < 4; ++i)
#pragma unroll
        for (int r = 0; r < 8; ++r)
            out[((size_t)b*CO + o0 + ty*4 + i)*PIX + px0 + tx + 16*r] = acc[i][r];
}

// ---------------- energies (unchanged) ---------------------------------------
__global__ void __launch_bounds__(256)
energyH_kernel(const float* __restrict__ q, const float* __restrict__ k,
               float* __restrict__ att)
{
    const int w = blockIdx.x, b = blockIdx.y;
    __shared__ float sQ[32][96], sK[32][96];
    const int tid = threadIdx.x;
    float acc[36];
#pragma unroll
    for (int i = 0; i < 36; ++i) acc[i] = 0.f;

    for (int c0 = 0; c0 < CQKX; c0 += 32) {
        __syncthreads();
        for (int idx = tid; idx < 32*96; idx += 256) {
            int c = idx / 96, p = idx % 96;
            size_t off = (size_t)(b*CQKX + c0 + c) * PIX + p*96 + w;
            sQ[c][p] = q[off];
            sK[c][p] = k[off];
        }
        __syncthreads();
#pragma unroll
        for (int it = 0; it < 36; ++it) {
            int oi = it*256 + tid;
            int h = oi / 96, gg = oi % 96;
            float s = acc[it];
#pragma unroll
            for (int c = 0; c < 32; ++c) s = fmaf(sQ[c][h], sK[c][gg], s);
            acc[it] = s;
        }
    }
#pragma unroll
    for (int it = 0; it < 36; ++it) {
        int oi = it*256 + tid;
        int h = oi / 96, gg = oi % 96;
        float vv = (gg == h) ? __int_as_float(0xff800000u) : acc[it];
        att[((size_t)((b*96 + h)*96 + w))*192 + gg] = vv;
    }
}

__global__ void __launch_bounds__(256)
energyW_kernel(const float* __restrict__ q, const float* __restrict__ k,
               float* __restrict__ att)
{
    const int h = blockIdx.x, b = blockIdx.y;
    __shared__ float sQ[32][96], sK[32][96];
    const int tid = threadIdx.x;
    float acc[36];
#pragma unroll
    for (int i = 0; i < 36; ++i) acc[i] = 0.f;

    for (int c0 = 0; c0 < CQKX; c0 += 32) {
        __syncthreads();
        for (int idx = tid; idx < 32*96; idx += 256) {
            int c = idx / 96, p = idx % 96;
            size_t off = (size_t)(b*CQKX + c0 + c) * PIX + h*96 + p;
            sQ[c][p] = q[off];
            sK[c][p] = k[off];
        }
        __syncthreads();
#pragma unroll
        for (int it = 0; it < 36; ++it) {
            int oi = it*256 + tid;
            int wc = oi / 96, v2 = oi % 96;
            float s = acc[it];
#pragma unroll
            for (int c = 0; c < 32; ++c) s = fmaf(sQ[c][wc], sK[c][v2], s);
            acc[it] = s;
        }
    }
#pragma unroll
    for (int it = 0; it < 36; ++it) {
        int oi = it*256 + tid;
        int wc = oi / 96, v2 = oi % 96;
        att[((size_t)((b*96 + h)*96 + wc))*192 + 96 + v2] = acc[it];
    }
}

// ---------------- softmax over 192 (unchanged) --------------------------------
__global__ void softmax_kernel(float* __restrict__ att)
{
    const int t = threadIdx.x;
    const size_t base = (size_t)blockIdx.x * 192;
    float v = att[base + t];
    __shared__ float red[6];

    float m = v;
#pragma unroll
    for (int o = 16; o; o >>= 1) m = fmaxf(m, __shfl_xor_sync(0xffffffffu, m, o));
    if ((t & 31) == 0) red[t >> 5] = m;
    __syncthreads();
    m = fmaxf(fmaxf(fmaxf(red[0], red[1]), fmaxf(red[2], red[3])),
              fmaxf(red[4], red[5]));

    float e = expf(v - m);
    float s = e;
#pragma unroll
    for (int o = 16; o; o >>= 1) s += __shfl_xor_sync(0xffffffffu, s, o);
    __syncthreads();
    if ((t & 31) == 0) red[t >> 5] = s;
    __syncthreads();
    s = red[0] + red[1] + red[2] + red[3] + red[4] + red[5];
    att[base + t] = e / s;
}

// ---------------- aggregation (unchanged) -------------------------------------
__global__ void __launch_bounds__(256)
aggH_kernel(const float* __restrict__ v, const float* __restrict__ att,
            const float* __restrict__ feat, const float* __restrict__ gp,
            float* __restrict__ dst)
{
    const int w = blockIdx.x, b = blockIdx.y;
    const int tid = threadIdx.x;
    __shared__ float sA2[96][97];
    __shared__ float sV[16][97];
    const float gm = *gp;

    for (int idx = tid; idx < 96*96; idx += 256) {
        int h = idx / 96, gg = idx % 96;
        sA2[h][gg] = att[((size_t)((b*96 + h)*96 + w))*192 + gg];
    }
    const int clg = tid >> 5;
    const int hq  = tid & 31;

    for (int c0 = 0; c0 < CIX; c0 += 16) {
        __syncthreads();
        for (int idx = tid; idx < 16*96; idx += 256) {
            int cl = idx / 96, gg = idx % 96;
            sV[cl][gg] = v[(size_t)(b*CIX + c0 + cl) * PIX + gg*96 + w];
        }
        __syncthreads();
        float a0[3] = {0.f,0.f,0.f}, a1[3] = {0.f,0.f,0.f};
#pragma unroll 4
        for (int gg = 0; gg < 96; ++gg) {
            float v0 = sV[clg*2][gg], v1 = sV[clg*2+1][gg];
#pragma unroll
            for (int r = 0; r < 3; ++r) {
                float a = sA2[hq + 32*r][gg];
                a0[r] = fmaf(v0, a, a0[r]);
                a1[r] = fmaf(v1, a, a1[r]);
            }
        }
#pragma unroll
        for (int r = 0; r < 3; ++r) {
            int h = hq + 32*r;
            size_t oi0 = ((size_t)(b*CIX + c0 + clg*2    )*96 + h)*96 + w;
            size_t oi1 = ((size_t)(b*CIX + c0 + clg*2 + 1)*96 + h)*96 + w;
            dst[oi0] = feat[oi0] + gm * a0[r];
            dst[oi1] = feat[oi1] + gm * a1[r];
        }
    }
}

__global__ void __launch_bounds__(256)
aggW_kernel(const float* __restrict__ v, const float* __restrict__ att,
            const float* __restrict__ gp, float* __restrict__ dst)
{
    const int h = blockIdx.x, b = blockIdx.y;
    const int tid = threadIdx.x;
    __shared__ float sA2[96][97];
    __shared__ float sV[16][97];
    const float gm = *gp;

    for (int idx = tid; idx < 96*96; idx += 256) {
        int wc = idx / 96, v2 = idx % 96;
        sA2[wc][v2] = att[((size_t)((b*96 + h)*96 + wc))*192 + 96 + v2];
    }
    const int clg = tid >> 5;
    const int wq  = tid & 31;

    for (int c0 = 0; c0 < CIX; c0 += 16) {
        __syncthreads();
        for (int idx = tid; idx < 16*96; idx += 256) {
            int cl = idx / 96, v2 = idx % 96;
            sV[cl][v2] = v[(size_t)(b*CIX + c0 + cl) * PIX + h*96 + v2];
        }
        __syncthreads();
        float a0[3] = {0.f,0.f,0.f}, a1[3] = {0.f,0.f,0.f};
#pragma unroll 4
        for (int v2 = 0; v2 < 96; ++v2) {
            float v0 = sV[clg*2][v2], v1 = sV[clg*2+1][v2];
#pragma unroll
            for (int r = 0; r < 3; ++r) {
                float a = sA2[wq + 32*r][v2];
                a0[r] = fmaf(v0, a, a0[r]);
                a1[r] = fmaf(v1, a, a1[r]);
            }
        }
#pragma unroll
        for (int r = 0; r < 3; ++r) {
            int wc = wq + 32*r;
            size_t oi0 = ((size_t)(b*CIX + c0 + clg*2    )*96 + h)*96 + wc;
            size_t oi1 = ((size_t)(b*CIX + c0 + clg*2 + 1)*96 + h)*96 + wc;
            dst[oi0] += gm * a0[r];
            dst[oi1] += gm * a1[r];
        }
    }
}

// ---------------- final 1x1 (unchanged) ---------------------------------------
__global__ void __launch_bounds__(256)
final_kernel(const float* __restrict__ in, const float* __restrict__ ow,
             const float* __restrict__ ob, float* __restrict__ out)
{
    const int px0 = blockIdx.x * 256;
    const int b   = blockIdx.y;
    const int tid = threadIdx.x;
    __shared__ float sIn[32][256];
    __shared__ float sW[19][32];
    float acc[NCL];
#pragma unroll
    for (int o = 0; o < NCL; ++o) acc[o] = 0.f;

    for (int c0 = 0; c0 < CIX; c0 += 32) {
        __syncthreads();
#pragma unroll
        for (int k = 0; k < 32; ++k)
            sIn[k][tid] = in[(size_t)(b*CIX + c0 + k) * PIX + px0 + tid];
        for (int idx = tid; idx < NCL*32; idx += 256)
            sW[idx >> 5][idx & 31] = ow[(size_t)(idx >> 5) * CIX + c0 + (idx & 31)];
        __syncthreads();
#pragma unroll
        for (int j = 0; j < 32; ++j) {
            float xv = sIn[j][tid];
#pragma unroll
            for (int o = 0; o < NCL; ++o) acc[o] = fmaf(sW[o][j], xv, acc[o]);
        }
    }
#pragma unroll
    for (int o = 0; o < NCL; ++o)
        out[((size_t)(b*NCL + o)) * PIX + px0 + tid] = acc[o] + ob[o];
}

// ---------------- launcher -----------------------------------------------------
extern "C" void kernel_launch(void* const* d_in, const int* in_sizes, int n_in,
                              void* d_out, int out_size)
{
    const float* x       = (const float*)d_in[0];
    const float* conva_w = (const float*)d_in[1];
    const float* bn1_s   = (const float*)d_in[2];
    const float* bn1_b   = (const float*)d_in[3];
    const float* q_w     = (const float*)d_in[4];
    const float* k_w     = (const float*)d_in[5];
    const float* v_w     = (const float*)d_in[6];
    const float* gamma   = (const float*)d_in[7];
    const float* convb_w = (const float*)d_in[8];
    const float* bn2_s   = (const float*)d_in[9];
    const float* bn2_b   = (const float*)d_in[10];
    const float* bott_w  = (const float*)d_in[11];
    const float* bn3_s   = (const float*)d_in[12];
    const float* bn3_b   = (const float*)d_in[13];
    const float* out_w   = (const float*)d_in[14];
    const float* out_b   = (const float*)d_in[15];
    float* out = (float*)d_out;

    float *pA, *pB, *pV, *pQ, *pK, *pAtt;
    cudaGetSymbolAddress((void**)&pA,   g_A);
    cudaGetSymbolAddress((void**)&pB,   g_Bf);
    cudaGetSymbolAddress((void**)&pV,   g_V);
    cudaGetSymbolAddress((void**)&pQ,   g_Q);
    cudaGetSymbolAddress((void**)&pK,   g_K);
    cudaGetSymbolAddress((void**)&pAtt, g_Att);

    cudaFuncSetAttribute(conv_tc_kernel,
                         cudaFuncAttributeMaxDynamicSharedMemorySize, CSM_TOTAL);

    dim3 cgrid(6, 12, BB * (CIX/128));   // (6,12,8), 256 threads, 2 CTA/SM

    // conva + bn1 + relu -> A   (bf16x2 split tensor cores)
    conv_tc_kernel<<<cgrid, 256, CSM_TOTAL>>>(x, conva_w, bn1_s, bn1_b, pA,
                                              CINX, CINX*9, 0, 2|4);

    // 2 recurrences of criss-cross attention (fp32, proven)
    for (int r = 0; r < 2; ++r) {
        const float* feat = r ? pB : pA;
        float*       dst  = r ? pA : pB;
        pw_kernel<<<dim3(72, 1, BB), 256>>>(feat, q_w, pQ, CIX, CQKX);
        pw_kernel<<<dim3(72, 1, BB), 256>>>(feat, k_w, pK, CIX, CQKX);
        pw_kernel<<<dim3(72, 8, BB), 256>>>(feat, v_w, pV, CIX, CIX);
        energyH_kernel<<<dim3(96, BB), 256>>>(pQ, pK, pAtt);
        energyW_kernel<<<dim3(96, BB), 256>>>(pQ, pK, pAtt);
        softmax_kernel<<<BB*PIX, 192>>>(pAtt);
        aggH_kernel<<<dim3(96, BB), 256>>>(pV, pAtt, feat, gamma, dst);
        aggW_kernel<<<dim3(96, BB), 256>>>(pV, pAtt, gamma, dst);
    }

    // convb + bn2 + relu : A -> B
    conv_tc_kernel<<<cgrid, 256, CSM_TOTAL>>>(pA, convb_w, bn2_s, bn2_b, pB,
                                              CIX, CIX*9, 0, 2|4);

    // bottleneck conv over virtual concat [x (2048ch), B (512ch)] -> V, bn3
    conv_tc_kernel<<<cgrid, 256, CSM_TOTAL>>>(x,  bott_w, nullptr, nullptr, pV,
                                              CINX, (CINX+CIX)*9, 0, 0);
    conv_tc_kernel<<<cgrid, 256, CSM_TOTAL>>>(pB, bott_w, bn3_s, bn3_b, pV,
                                              CIX, (CINX+CIX)*9, CINX*9, 1|2);

    // final 1x1 -> d_out
    final_kernel<<<dim3(PIX/256, BB), 256>>>(pV, out_w, out_b, out);
}

// round 14
// speedup vs baseline: 2.2142x; 1.1291x over previous
#include <cuda_runtime.h>
#include <cuda_fp16.h>
#include <math.h>
#include <cstdint>

#define BB   2
#define HH   96
#define WW   96
#define PIX  (HH*WW)        // 9216
#define CINX 2048
#define CIX  512
#define CQKX 64
#define NCL  19

// ---------------- scratch (static device globals; no allocation) ------------
__device__ float g_A  [BB*CIX*PIX];
__device__ float g_Bf [BB*CIX*PIX];
__device__ float g_V  [BB*CIX*PIX];
__device__ float g_Q  [BB*CQKX*PIX];
__device__ float g_K  [BB*CQKX*PIX];
__device__ float g_Att[BB*PIX*192];

// ---------------- fp16x2 split helpers ---------------------------------------
// x = hi + lo, hi = f16(x), lo = f16(x - hi). Effective precision ~2^-22.
__device__ __forceinline__ void split2h(float x0, float x1,
                                        uint32_t& hi, uint32_t& lo) {
    __half h0 = __float2half_rn(x0);
    __half h1 = __float2half_rn(x1);
    __half l0 = __float2half_rn(x0 - __half2float(h0));
    __half l1 = __float2half_rn(x1 - __half2float(h1));
    hi = (uint32_t)__half_as_ushort(h0) | ((uint32_t)__half_as_ushort(h1) << 16);
    lo = (uint32_t)__half_as_ushort(l0) | ((uint32_t)__half_as_ushort(l1) << 16);
}

// m16n8k16 f16 MMA; accumulator layout identical to bf16 variant.
#define MMA_F16(d, a, b0, b1)                                                   \
    asm volatile("mma.sync.aligned.m16n8k16.row.col.f32.f16.f16.f32 "           \
        "{%0,%1,%2,%3}, {%4,%5,%6,%7}, {%8,%9}, {%0,%1,%2,%3};"                  \
        : "+f"((d)[0]), "+f"((d)[1]), "+f"((d)[2]), "+f"((d)[3])                 \
        : "r"((a)[0]), "r"((a)[1]), "r"((a)[2]), "r"((a)[3]),                    \
          "r"(b0), "r"(b1))

// ============ fp16x2 split mma.sync implicit-GEMM 3x3 conv ===================
// block: 128 co x 128 px (8 rows x 16 cols). 256 thr = 8 warps (4 co x 2 px).
// warp tile 32co x 64px. K = Cin*9, chunked by 32 (= 16 f16 pairs).
// Double-buffered A/B tiles, 1 barrier per chunk, weights prefetched 1 chunk
// ahead in registers. smem row stride 20 u32 (conflict-free fragments).
#define PADK   20
#define TILEU  2560                        // u32 per tile (128*20) = 10240 B
#define CSM_PATCH 0                        // 32 x 10 x 18 f32 = 23040 B
#define CSM_TILES 23040                    // 8 tiles (AH0 AH1 AL0 AL1 BH0 BH1 BL0 BL1)
#define CSM_TOTAL (23040 + 8*10240)        // 104960 B

// im2col build for one 16-k half, KB is a compile-time base.
#define BUILD_B_HALF(KB) do {                                                   \
    _Pragma("unroll")                                                           \
    for (int jp = 0; jp < 8; ++jp) {                                            \
        const int k0 = (KB) + 2*jp, k1 = k0 + 1;                                \
        const int cl0 = k0/9, tp0 = k0 - cl0*9;                                 \
        const int cl1 = k1/9, tp1 = k1 - cl1*9;                                 \
        const int dy0 = tp0/3, dx0 = tp0 - dy0*3;                               \
        const int dy1 = tp1/3, dx1 = tp1 - dy1*3;                               \
        float v0 = sPatch[cl0*180 + dy0*18 + pb + dx0];                         \
        float v1 = sPatch[cl1*180 + dy1*18 + pb + dx1];                         \
        split2h(v0, v1, hb[jp], lb[jp]);                                        \
    }                                                                           \
} while (0)

__global__ void __launch_bounds__(256, 2)
conv_tc_kernel(const float* __restrict__ in, const float* __restrict__ wgt,
               const float* __restrict__ scale, const float* __restrict__ bias,
               float* __restrict__ outp, int Cin, int WCin9, int coff9, int flags)
{
    extern __shared__ char smem[];
    float*    sPatch = (float*)(smem + CSM_PATCH);
    uint32_t* tiles  = (uint32_t*)(smem + CSM_TILES);

    const int tid  = threadIdx.x;
    const int lane = tid & 31;
    const int wid  = tid >> 5;
    const int g    = lane >> 2;          // group 0..7
    const int tig  = lane & 3;           // thread-in-group 0..3
    const int mw   = (wid & 3) * 32;     // warp co offset
    const int nw   = (wid >> 2) * 64;    // warp px offset

    const int tile_w = blockIdx.x * 16;
    const int tile_h = blockIdx.y * 8;
    const int b      = blockIdx.z >> 2;
    const int co0    = (blockIdx.z & 3) * 128;

    float acc[2][8][4];
#pragma unroll
    for (int mi = 0; mi < 2; ++mi)
#pragma unroll
        for (int ni = 0; ni < 8; ++ni)
#pragma unroll
            for (int q = 0; q < 4; ++q) acc[mi][ni][q] = 0.f;

    const float* inb = in + (size_t)b * Cin * PIX;
    const int groups = Cin >> 5;
    const int nsteps = groups * 9;

    // A-staging assignment: co = (tid>>3) + 32*i, j4 = tid&7 (same all i)
    const int coA = tid >> 3;
    const int j4A = tid & 7;
    const float* wpA = wgt + coff9 + (size_t)(co0 + coA) * WCin9 + j4A * 4;

    // B-build assignment: px = tid>>1, k-half = (tid&1)
    const int px_b = tid >> 1;
    const int kp_b = (tid & 1) * 8;
    const int pb   = (px_b >> 4) * 18 + (px_b & 15);   // patch base offset

    // prologue: prefetch weights for step 0
    float4 wpre[4];
#pragma unroll
    for (int i = 0; i < 4; ++i)
        wpre[i] = *(const float4*)(wpA + (size_t)(32 * i) * WCin9);

    int buf = 0;
    for (int grp = 0; grp < groups; ++grp) {
        // ---- stage input patch: 32 cin x 10 x 18 (zero halo) ----
        for (int idx = tid; idx < 32 * 180; idx += 256) {
            int c = idx / 180, rem = idx % 180;
            int pr = rem / 18, pc = rem % 18;
            int gh = tile_h - 1 + pr, gw = tile_w - 1 + pc;
            float v = 0.f;
            if ((unsigned)gh < 96u && (unsigned)gw < 96u)
                v = inb[(size_t)(grp * 32 + c) * PIX + gh * 96 + gw];
            sPatch[idx] = v;
        }
        __syncthreads();   // patch ready (also: all builds of prev grp done)

#pragma unroll
        for (int c9 = 0; c9 < 9; ++c9) {
            uint32_t* sAh = tiles + buf * TILEU;
            uint32_t* sAl = tiles + (2 + buf) * TILEU;
            uint32_t* sBh = tiles + (4 + buf) * TILEU;
            uint32_t* sBl = tiles + (6 + buf) * TILEU;

            // ---- store prefetched A: 128co x 32k f16 hi/lo pairs ----
            {
                const int d0 = coA * PADK + j4A * 2;
#pragma unroll
                for (int i = 0; i < 4; ++i) {
                    uint32_t h0, l0, h1, l1;
                    split2h(wpre[i].x, wpre[i].y, h0, l0);
                    split2h(wpre[i].z, wpre[i].w, h1, l1);
                    const int d = d0 + i * 32 * PADK;
                    sAh[d] = h0; sAh[d + 1] = h1;
                    sAl[d] = l0; sAl[d + 1] = l1;
                }
            }
            // ---- build B: im2col 128px x (16k half) -> f16 hi/lo pairs ----
            {
                uint32_t hb[8], lb[8];
                if ((tid & 1) == 0) { BUILD_B_HALF(c9 * 32); }
                else                { BUILD_B_HALF(c9 * 32 + 16); }
                uint32_t* dh = sBh + px_b * PADK + kp_b;
                uint32_t* dl = sBl + px_b * PADK + kp_b;
                *(uint4*)(dh)     = make_uint4(hb[0], hb[1], hb[2], hb[3]);
                *(uint4*)(dh + 4) = make_uint4(hb[4], hb[5], hb[6], hb[7]);
                *(uint4*)(dl)     = make_uint4(lb[0], lb[1], lb[2], lb[3]);
                *(uint4*)(dl + 4) = make_uint4(lb[4], lb[5], lb[6], lb[7]);
            }
            // ---- prefetch weights for next chunk ----
            {
                const int nstep = grp * 9 + c9 + 1;
                if (nstep < nsteps) {
                    const float* wp = wpA + (size_t)nstep * 32;
#pragma unroll
                    for (int i = 0; i < 4; ++i)
                        wpre[i] = *(const float4*)(wp + (size_t)(32 * i) * WCin9);
                }
            }
            __syncthreads();   // tiles[buf] ready; prior-prior MMAs done

            // ---- compute: 2 k16-steps x 8 ni x (hh + hl + lh) ----
#pragma unroll
            for (int ks = 0; ks < 2; ++ks) {
                const int kb = ks * 8;
                uint32_t ah[2][4], al[2][4];
#pragma unroll
                for (int mi = 0; mi < 2; ++mi) {
                    const uint32_t* aph = sAh + (mw + mi * 16 + g) * PADK + kb + tig;
                    ah[mi][0] = aph[0];
                    ah[mi][1] = aph[8 * PADK];
                    ah[mi][2] = aph[4];
                    ah[mi][3] = aph[8 * PADK + 4];
                    const uint32_t* apl = sAl + (mw + mi * 16 + g) * PADK + kb + tig;
                    al[mi][0] = apl[0];
                    al[mi][1] = apl[8 * PADK];
                    al[mi][2] = apl[4];
                    al[mi][3] = apl[8 * PADK + 4];
                }
#pragma unroll
                for (int ni = 0; ni < 8; ++ni) {
                    const uint32_t* bph = sBh + (nw + ni * 8 + g) * PADK + kb + tig;
                    uint32_t b0h = bph[0], b1h = bph[4];
                    const uint32_t* bpl = sBl + (nw + ni * 8 + g) * PADK + kb + tig;
                    uint32_t b0l = bpl[0], b1l = bpl[4];
                    MMA_F16(acc[0][ni], ah[0], b0h, b1h);
                    MMA_F16(acc[1][ni], ah[1], b0h, b1h);
                    MMA_F16(acc[0][ni], ah[0], b0l, b1l);
                    MMA_F16(acc[1][ni], ah[1], b0l, b1l);
                    MMA_F16(acc[0][ni], al[0], b0h, b1h);
                    MMA_F16(acc[1][ni], al[1], b0h, b1h);
                }
            }
            buf ^= 1;
        }
    }

    // ---- epilogue: acc -> gmem (bn / relu / accumulate) ----
#pragma unroll
    for (int mi = 0; mi < 2; ++mi) {
#pragma unroll
        for (int rr = 0; rr < 2; ++rr) {
            int co = co0 + mw + mi * 16 + g + rr * 8;
            float s = 1.f, bs = 0.f;
            if (flags & 2) { s = scale[co]; bs = bias[co]; }
            const size_t obase = ((size_t)(b * 512 + co)) * PIX;
#pragma unroll
            for (int ni = 0; ni < 8; ++ni) {
#pragma unroll
                for (int cc = 0; cc < 2; ++cc) {
                    int px = nw + ni * 8 + 2 * tig + cc;
                    size_t oi = obase + (size_t)(tile_h + (px >> 4)) * 96
                              + tile_w + (px & 15);
                    float v = acc[mi][ni][rr * 2 + cc];
                    if (flags & 1) v += outp[oi];
                    v = v * s + bs;
                    if (flags & 4) v = fmaxf(v, 0.f);
                    outp[oi] = v;
                }
            }
        }
    }
}

// ---------------- 1x1 projection (unchanged, proven) -------------------------
__global__ void __launch_bounds__(256)
pw_kernel(const float* __restrict__ in, const float* __restrict__ wgt,
          float* __restrict__ out, int Cin, int CO)
{
    const int px0 = blockIdx.x * 128;
    const int o0  = blockIdx.y * 64;
    const int b   = blockIdx.z;
    __shared__ float sIn[16][128];
    __shared__ float sW[64][17];
    const int tid = threadIdx.x, tx = tid & 15, ty = tid >> 4;
    float acc[4][8];
#pragma unroll
    for (int i = 0; i < 4; ++i)
#pragma unroll
        for (int r = 0; r < 8; ++r) acc[i][r] = 0.f;

    const float* inb = in + (size_t)b * Cin * PIX;
    for (int c0 = 0; c0 < Cin; c0 += 16) {
        __syncthreads();
#pragma unroll
        for (int k = 0; k < 8; ++k) {
            int idx = tid + k*256;
            sIn[idx >> 7][idx & 127] =
                inb[(size_t)(c0 + (idx >> 7)) * PIX + px0 + (idx & 127)];
        }
#pragma unroll
        for (int k = 0; k < 4; ++k) {
            int idx = tid + k*256;
            sW[idx >> 4][idx & 15] =
                wgt[(size_t)(o0 + (idx >> 4)) * Cin + c0 + (idx & 15)];
        }
        __syncthreads();
#pragma unroll
        for (int j = 0; j < 16; ++j) {
            float iv[8];
#pragma unroll
            for (int r = 0; r < 8; ++r) iv[r] = sIn[j][tx + 16*r];
#pragma unroll
            for (int i = 0; i < 4; ++i) {
                float wv = sW[ty*4 + i][j];
#pragma unroll
                for (int r = 0; r < 8; ++r)
                    acc[i][r] = fmaf(wv, iv[r], acc[i][r]);
            }
        }
    }
#pragma unroll
    for (int i = 0; i < 4; ++i)
#pragma unroll
        for (int r = 0; r < 8; ++r)
            out[((size_t)b*CO + o0 + ty*4 + i)*PIX + px0 + tx + 16*r] = acc[i][r];
}

// ---------------- energies (unchanged) ---------------------------------------
__global__ void __launch_bounds__(256)
energyH_kernel(const float* __restrict__ q, const float* __restrict__ k,
               float* __restrict__ att)
{
    const int w = blockIdx.x, b = blockIdx.y;
    __shared__ float sQ[32][96], sK[32][96];
    const int tid = threadIdx.x;
    float acc[36];
#pragma unroll
    for (int i = 0; i < 36; ++i) acc[i] = 0.f;

    for (int c0 = 0; c0 < CQKX; c0 += 32) {
        __syncthreads();
        for (int idx = tid; idx < 32*96; idx += 256) {
            int c = idx / 96, p = idx % 96;
            size_t off = (size_t)(b*CQKX + c0 + c) * PIX + p*96 + w;
            sQ[c][p] = q[off];
            sK[c][p] = k[off];
        }
        __syncthreads();
#pragma unroll
        for (int it = 0; it < 36; ++it) {
            int oi = it*256 + tid;
            int h = oi / 96, gg = oi % 96;
            float s = acc[it];
#pragma unroll
            for (int c = 0; c < 32; ++c) s = fmaf(sQ[c][h], sK[c][gg], s);
            acc[it] = s;
        }
    }
#pragma unroll
    for (int it = 0; it < 36; ++it) {
        int oi = it*256 + tid;
        int h = oi / 96, gg = oi % 96;
        float vv = (gg == h) ? __int_as_float(0xff800000u) : acc[it];
        att[((size_t)((b*96 + h)*96 + w))*192 + gg] = vv;
    }
}

__global__ void __launch_bounds__(256)
energyW_kernel(const float* __restrict__ q, const float* __restrict__ k,
               float* __restrict__ att)
{
    const int h = blockIdx.x, b = blockIdx.y;
    __shared__ float sQ[32][96], sK[32][96];
    const int tid = threadIdx.x;
    float acc[36];
#pragma unroll
    for (int i = 0; i < 36; ++i) acc[i] = 0.f;

    for (int c0 = 0; c0 < CQKX; c0 += 32) {
        __syncthreads();
        for (int idx = tid; idx < 32*96; idx += 256) {
            int c = idx / 96, p = idx % 96;
            size_t off = (size_t)(b*CQKX + c0 + c) * PIX + h*96 + p;
            sQ[c][p] = q[off];
            sK[c][p] = k[off];
        }
        __syncthreads();
#pragma unroll
        for (int it = 0; it < 36; ++it) {
            int oi = it*256 + tid;
            int wc = oi / 96, v2 = oi % 96;
            float s = acc[it];
#pragma unroll
            for (int c = 0; c < 32; ++c) s = fmaf(sQ[c][wc], sK[c][v2], s);
            acc[it] = s;
        }
    }
#pragma unroll
    for (int it = 0; it < 36; ++it) {
        int oi = it*256 + tid;
        int wc = oi / 96, v2 = oi % 96;
        att[((size_t)((b*96 + h)*96 + wc))*192 + 96 + v2] = acc[it];
    }
}

// ---------------- softmax over 192 (unchanged) --------------------------------
__global__ void softmax_kernel(float* __restrict__ att)
{
    const int t = threadIdx.x;
    const size_t base = (size_t)blockIdx.x * 192;
    float v = att[base + t];
    __shared__ float red[6];

    float m = v;
#pragma unroll
    for (int o = 16; o; o >>= 1) m = fmaxf(m, __shfl_xor_sync(0xffffffffu, m, o));
    if ((t & 31) == 0) red[t >> 5] = m;
    __syncthreads();
    m = fmaxf(fmaxf(fmaxf(red[0], red[1]), fmaxf(red[2], red[3])),
              fmaxf(red[4], red[5]));

    float e = expf(v - m);
    float s = e;
#pragma unroll
    for (int o = 16; o; o >>= 1) s += __shfl_xor_sync(0xffffffffu, s, o);
    __syncthreads();
    if ((t & 31) == 0) red[t >> 5] = s;
    __syncthreads();
    s = red[0] + red[1] + red[2] + red[3] + red[4] + red[5];
    att[base + t] = e / s;
}

// ---------------- aggregation (unchanged) -------------------------------------
__global__ void __launch_bounds__(256)
aggH_kernel(const float* __restrict__ v, const float* __restrict__ att,
            const float* __restrict__ feat, const float* __restrict__ gp,
            float* __restrict__ dst)
{
    const int w = blockIdx.x, b = blockIdx.y;
    const int tid = threadIdx.x;
    __shared__ float sA2[96][97];
    __shared__ float sV[16][97];
    const float gm = *gp;

    for (int idx = tid; idx < 96*96; idx += 256) {
        int h = idx / 96, gg = idx % 96;
        sA2[h][gg] = att[((size_t)((b*96 + h)*96 + w))*192 + gg];
    }
    const int clg = tid >> 5;
    const int hq  = tid & 31;

    for (int c0 = 0; c0 < CIX; c0 += 16) {
        __syncthreads();
        for (int idx = tid; idx < 16*96; idx += 256) {
            int cl = idx / 96, gg = idx % 96;
            sV[cl][gg] = v[(size_t)(b*CIX + c0 + cl) * PIX + gg*96 + w];
        }
        __syncthreads();
        float a0[3] = {0.f,0.f,0.f}, a1[3] = {0.f,0.f,0.f};
#pragma unroll 4
        for (int gg = 0; gg < 96; ++gg) {
            float v0 = sV[clg*2][gg], v1 = sV[clg*2+1][gg];
#pragma unroll
            for (int r = 0; r < 3; ++r) {
                float a = sA2[hq + 32*r][gg];
                a0[r] = fmaf(v0, a, a0[r]);
                a1[r] = fmaf(v1, a, a1[r]);
            }
        }
#pragma unroll
        for (int r = 0; r < 3; ++r) {
            int h = hq + 32*r;
            size_t oi0 = ((size_t)(b*CIX + c0 + clg*2    )*96 + h)*96 + w;
            size_t oi1 = ((size_t)(b*CIX + c0 + clg*2 + 1)*96 + h)*96 + w;
            dst[oi0] = feat[oi0] + gm * a0[r];
            dst[oi1] = feat[oi1] + gm * a1[r];
        }
    }
}

__global__ void __launch_bounds__(256)
aggW_kernel(const float* __restrict__ v, const float* __restrict__ att,
            const float* __restrict__ gp, float* __restrict__ dst)
{
    const int h = blockIdx.x, b = blockIdx.y;
    const int tid = threadIdx.x;
    __shared__ float sA2[96][97];
    __shared__ float sV[16][97];
    const float gm = *gp;

    for (int idx = tid; idx < 96*96; idx += 256) {
        int wc = idx / 96, v2 = idx % 96;
        sA2[wc][v2] = att[((size_t)((b*96 + h)*96 + wc))*192 + 96 + v2];
    }
    const int clg = tid >> 5;
    const int wq  = tid & 31;

    for (int c0 = 0; c0 < CIX; c0 += 16) {
        __syncthreads();
        for (int idx = tid; idx < 16*96; idx += 256) {
            int cl = idx / 96, v2 = idx % 96;
            sV[cl][v2] = v[(size_t)(b*CIX + c0 + cl) * PIX + h*96 + v2];
        }
        __syncthreads();
        float a0[3] = {0.f,0.f,0.f}, a1[3] = {0.f,0.f,0.f};
#pragma unroll 4
        for (int v2 = 0; v2 < 96; ++v2) {
            float v0 = sV[clg*2][v2], v1 = sV[clg*2+1][v2];
#pragma unroll
            for (int r = 0; r < 3; ++r) {
                float a = sA2[wq + 32*r][v2];
                a0[r] = fmaf(v0, a, a0[r]);
                a1[r] = fmaf(v1, a, a1[r]);
            }
        }
#pragma unroll
        for (int r = 0; r < 3; ++r) {
            int wc = wq + 32*r;
            size_t oi0 = ((size_t)(b*CIX + c0 + clg*2    )*96 + h)*96 + wc;
            size_t oi1 = ((size_t)(b*CIX + c0 + clg*2 + 1)*96 + h)*96 + wc;
            dst[oi0] += gm * a0[r];
            dst[oi1] += gm * a1[r];
        }
    }
}

// ---------------- final 1x1 (unchanged) ---------------------------------------
__global__ void __launch_bounds__(256)
final_kernel(const float* __restrict__ in, const float* __restrict__ ow,
             const float* __restrict__ ob, float* __restrict__ out)
{
    const int px0 = blockIdx.x * 256;
    const int b   = blockIdx.y;
    const int tid = threadIdx.x;
    __shared__ float sIn[32][256];
    __shared__ float sW[19][32];
    float acc[NCL];
#pragma unroll
    for (int o = 0; o < NCL; ++o) acc[o] = 0.f;

    for (int c0 = 0; c0 < CIX; c0 += 32) {
        __syncthreads();
#pragma unroll
        for (int k = 0; k < 32; ++k)
            sIn[k][tid] = in[(size_t)(b*CIX + c0 + k) * PIX + px0 + tid];
        for (int idx = tid; idx < NCL*32; idx += 256)
            sW[idx >> 5][idx & 31] = ow[(size_t)(idx >> 5) * CIX + c0 + (idx & 31)];
        __syncthreads();
#pragma unroll
        for (int j = 0; j < 32; ++j) {
            float xv = sIn[j][tid];
#pragma unroll
            for (int o = 0; o < NCL; ++o) acc[o] = fmaf(sW[o][j], xv, acc[o]);
        }
    }
#pragma unroll
    for (int o = 0; o < NCL; ++o)
        out[((size_t)(b*NCL + o)) * PIX + px0 + tid] = acc[o] + ob[o];
}

// ---------------- launcher -----------------------------------------------------
extern "C" void kernel_launch(void* const* d_in, const int* in_sizes, int n_in,
                              void* d_out, int out_size)
{
    const float* x       = (const float*)d_in[0];
    const float* conva_w = (const float*)d_in[1];
    const float* bn1_s   = (const float*)d_in[2];
    const float* bn1_b   = (const float*)d_in[3];
    const float* q_w     = (const float*)d_in[4];
    const float* k_w     = (const float*)d_in[5];
    const float* v_w     = (const float*)d_in[6];
    const float* gamma   = (const float*)d_in[7];
    const float* convb_w = (const float*)d_in[8];
    const float* bn2_s   = (const float*)d_in[9];
    const float* bn2_b   = (const float*)d_in[10];
    const float* bott_w  = (const float*)d_in[11];
    const float* bn3_s   = (const float*)d_in[12];
    const float* bn3_b   = (const float*)d_in[13];
    const float* out_w   = (const float*)d_in[14];
    const float* out_b   = (const float*)d_in[15];
    float* out = (float*)d_out;

    float *pA, *pB, *pV, *pQ, *pK, *pAtt;
    cudaGetSymbolAddress((void**)&pA,   g_A);
    cudaGetSymbolAddress((void**)&pB,   g_Bf);
    cudaGetSymbolAddress((void**)&pV,   g_V);
    cudaGetSymbolAddress((void**)&pQ,   g_Q);
    cudaGetSymbolAddress((void**)&pK,   g_K);
    cudaGetSymbolAddress((void**)&pAtt, g_Att);

    cudaFuncSetAttribute(conv_tc_kernel,
                         cudaFuncAttributeMaxDynamicSharedMemorySize, CSM_TOTAL);

    dim3 cgrid(6, 12, BB * (CIX/128));   // (6,12,8), 256 threads, 2 CTA/SM

    // conva + bn1 + relu -> A   (fp16x2 split tensor cores)
    conv_tc_kernel<<<cgrid, 256, CSM_TOTAL>>>(x, conva_w, bn1_s, bn1_b, pA,
                                              CINX, CINX*9, 0, 2|4);

    // 2 recurrences of criss-cross attention (fp32, proven)
    for (int r = 0; r < 2; ++r) {
        const float* feat = r ? pB : pA;
        float*       dst  = r ? pA : pB;
        pw_kernel<<<dim3(72, 1, BB), 256>>>(feat, q_w, pQ, CIX, CQKX);
        pw_kernel<<<dim3(72, 1, BB), 256>>>(feat, k_w, pK, CIX, CQKX);
        pw_kernel<<<dim3(72, 8, BB), 256>>>(feat, v_w, pV, CIX, CIX);
        energyH_kernel<<<dim3(96, BB), 256>>>(pQ, pK, pAtt);
        energyW_kernel<<<dim3(96, BB), 256>>>(pQ, pK, pAtt);
        softmax_kernel<<<BB*PIX, 192>>>(pAtt);
        aggH_kernel<<<dim3(96, BB), 256>>>(pV, pAtt, feat, gamma, dst);
        aggW_kernel<<<dim3(96, BB), 256>>>(pV, pAtt, gamma, dst);
    }

    // convb + bn2 + relu : A -> B
    conv_tc_kernel<<<cgrid, 256, CSM_TOTAL>>>(pA, convb_w, bn2_s, bn2_b, pB,
                                              CIX, CIX*9, 0, 2|4);

    // bottleneck conv over virtual concat [x (2048ch), B (512ch)] -> V, bn3
    conv_tc_kernel<<<cgrid, 256, CSM_TOTAL>>>(x,  bott_w, nullptr, nullptr, pV,
                                              CINX, (CINX+CIX)*9, 0, 0);
    conv_tc_kernel<<<cgrid, 256, CSM_TOTAL>>>(pB, bott_w, bn3_s, bn3_b, pV,
                                              CIX, (CINX+CIX)*9, CINX*9, 1|2);

    // final 1x1 -> d_out
    final_kernel<<<dim3(PIX/256, BB), 256>>>(pV, out_w, out_b, out);
}

// round 15
// speedup vs baseline: 2.5430x; 1.1485x over previous
#include <cuda_runtime.h>
#include <cuda_fp16.h>
#include <math.h>
#include <cstdint>

#define BB   2
#define HH   96
#define WW   96
#define PIX  (HH*WW)        // 9216
#define CINX 2048
#define CIX  512
#define CQKX 64
#define NCL  19

// ---------------- scratch (static device globals; no allocation) ------------
__device__ float g_A  [BB*CIX*PIX];
__device__ float g_Bf [BB*CIX*PIX];
__device__ float g_V  [BB*CIX*PIX];
__device__ float g_Q  [BB*CQKX*PIX];
__device__ float g_K  [BB*CQKX*PIX];
__device__ float g_Att[BB*PIX*192];
// pre-split weights (hi f16 | lo f16 << 16), same linear layout as fp32 weights
__device__ uint32_t g_Wa[CIX * CINX * 9];          // 9.4M
__device__ uint32_t g_Wb[CIX * CIX * 9];           // 2.4M
__device__ uint32_t g_Wt[CIX * (CINX + CIX) * 9];  // 11.8M

// ---------------- fp16 split helpers -----------------------------------------
__device__ __forceinline__ uint32_t packsplit(float x) {
    __half h = __float2half_rn(x);
    __half l = __float2half_rn(x - __half2float(h));
    return (uint32_t)__half_as_ushort(h) | ((uint32_t)__half_as_ushort(l) << 16);
}

__global__ void __launch_bounds__(256)
prep_w_kernel(const float* __restrict__ w, uint32_t* __restrict__ o, int n)
{
    int i = blockIdx.x * 256 + threadIdx.x;
    if (i < n) o[i] = packsplit(w[i]);
}

// m16n8k16 f16 MMA
#define MMA_F16(d, a, b0, b1)                                                   \
    asm volatile("mma.sync.aligned.m16n8k16.row.col.f32.f16.f16.f32 "           \
        "{%0,%1,%2,%3}, {%4,%5,%6,%7}, {%8,%9}, {%0,%1,%2,%3};"                  \
        : "+f"((d)[0]), "+f"((d)[1]), "+f"((d)[2]), "+f"((d)[3])                 \
        : "r"((a)[0]), "r"((a)[1]), "r"((a)[2]), "r"((a)[3]),                    \
          "r"(b0), "r"(b1))

#define LDSM_X4(R0, R1, R2, R3, A)                                              \
    asm volatile("ldmatrix.sync.aligned.m8n8.x4.shared.b16 {%0,%1,%2,%3}, [%4];" \
        : "=r"(R0), "=r"(R1), "=r"(R2), "=r"(R3) : "r"(A))

__device__ __forceinline__ uint32_t smem_u32(const void* p) {
    uint32_t a;
    asm("{ .reg .u64 t; cvta.to.shared.u64 t, %1; cvt.u32.u64 %0, t; }"
        : "=r"(a) : "l"(p));
    return a;
}

// ============ fp16-split mma.sync implicit-GEMM 3x3 conv (ldmatrix) ==========
// block: 128 co x 128 px. 256 thr = 8 warps (4 co x 2 px). warp 32co x 64px.
// K = Cin*9 chunked by 32. Patch pre-split packed u32; weights pre-split gmem.
// Tiles [row][PADK u32] rows = 80 B (16B-aligned, LDSM conflict-free).
#define PADK   20
#define TILEU  2560                       // u32 per tile
#define TILEB  10240                      // bytes per tile
#define CSM_PATCH 0                       // 32x10x18 packed u32 = 23040 B
#define CSM_TILES 23040                   // AH0 AH1 AL0 AL1 BH0 BH1 BL0 BL1
#define CSM_TOTAL (23040 + 8*TILEB)       // 104960 B

#define BUILD_B_HALF(KB) do {                                                   \
    _Pragma("unroll")                                                           \
    for (int jp = 0; jp < 8; ++jp) {                                            \
        const int k0 = (KB) + 2*jp, k1 = k0 + 1;                                \
        const int cl0 = k0/9, tp0 = k0 - cl0*9;                                 \
        const int cl1 = k1/9, tp1 = k1 - cl1*9;                                 \
        const int dy0 = tp0/3, dx0 = tp0 - dy0*3;                               \
        const int dy1 = tp1/3, dx1 = tp1 - dy1*3;                               \
        uint32_t w0 = sPatch[cl0*180 + dy0*18 + pb + dx0];                      \
        uint32_t w1 = sPatch[cl1*180 + dy1*18 + pb + dx1];                      \
        hb[jp] = __byte_perm(w0, w1, 0x5410);                                   \
        lb[jp] = __byte_perm(w0, w1, 0x7632);                                   \
    }                                                                           \
} while (0)

__global__ void __launch_bounds__(256, 2)
conv_tc_kernel(const float* __restrict__ in, const uint32_t* __restrict__ wgt,
               const float* __restrict__ scale, const float* __restrict__ bias,
               float* __restrict__ outp, int Cin, int WCin9, int coff9, int flags)
{
    extern __shared__ char smem[];
    uint32_t* sPatch = (uint32_t*)(smem + CSM_PATCH);
    const uint32_t sb = smem_u32(smem);

    const int tid  = threadIdx.x;
    const int lane = tid & 31;
    const int wid  = tid >> 5;
    const int g    = lane >> 2;
    const int tig  = lane & 3;
    const int mw   = (wid & 3) * 32;     // warp co offset
    const int nw   = (wid >> 2) * 64;    // warp px offset

    const int tile_w = blockIdx.x * 16;
    const int tile_h = blockIdx.y * 8;
    const int b      = blockIdx.z >> 2;
    const int co0    = (blockIdx.z & 3) * 128;

    float acc[2][8][4];
#pragma unroll
    for (int mi = 0; mi < 2; ++mi)
#pragma unroll
        for (int ni = 0; ni < 8; ++ni)
#pragma unroll
            for (int q = 0; q < 4; ++q) acc[mi][ni][q] = 0.f;

    const float* inb = in + (size_t)b * Cin * PIX;
    const int groups = Cin >> 5;
    const int nsteps = groups * 9;

    // A-staging: co = (tid>>3) + 32*i, j4 = tid&7
    const int coA = tid >> 3;
    const int j4A = tid & 7;
    const uint32_t* wpA = wgt + coff9 + (size_t)(co0 + coA) * WCin9 + j4A * 4;

    // B-build: px = tid>>1, k-half = tid&1
    const int px_b = tid >> 1;
    const int kp_b = (tid & 1) * 8;
    const int pb   = (px_b >> 4) * 18 + (px_b & 15);

    // ldmatrix per-lane address offsets (bytes, within a tile)
    const int mm = lane >> 3, rr8 = lane & 7;
    const uint32_t aOff = (uint32_t)((mw + (mm & 1) * 8 + rr8) * 80 + (mm >> 1) * 16);
    const uint32_t bOff = (uint32_t)((nw + ((mm >> 1) & 1) * 8 + rr8) * 80 + (mm & 1) * 16);

    // prologue: prefetch weights for step 0
    uint4 wpre[4];
#pragma unroll
    for (int i = 0; i < 4; ++i)
        wpre[i] = *(const uint4*)(wpA + (size_t)(32 * i) * WCin9);

    int buf = 0;
    for (int grp = 0; grp < groups; ++grp) {
        // ---- stage input patch pre-split: 32 cin x 10 x 18 (zero halo) ----
        for (int idx = tid; idx < 32 * 180; idx += 256) {
            int c = idx / 180, rem = idx % 180;
            int pr = rem / 18, pc = rem % 18;
            int gh = tile_h - 1 + pr, gw = tile_w - 1 + pc;
            float v = 0.f;
            if ((unsigned)gh < 96u && (unsigned)gw < 96u)
                v = inb[(size_t)(grp * 32 + c) * PIX + gh * 96 + gw];
            sPatch[idx] = packsplit(v);
        }
        __syncthreads();   // patch ready; prev group fully consumed

#pragma unroll
        for (int c9 = 0; c9 < 9; ++c9) {
            uint32_t* sAh = (uint32_t*)(smem + CSM_TILES + buf * TILEB);
            uint32_t* sAl = (uint32_t*)(smem + CSM_TILES + (2 + buf) * TILEB);
            uint32_t* sBh = (uint32_t*)(smem + CSM_TILES + (4 + buf) * TILEB);
            uint32_t* sBl = (uint32_t*)(smem + CSM_TILES + (6 + buf) * TILEB);

            // ---- store prefetched A (pre-split) via byte_perm ----
            {
                const int d0 = coA * PADK + j4A * 2;
#pragma unroll
                for (int i = 0; i < 4; ++i) {
                    const uint4 w = wpre[i];
                    const int d = d0 + i * 32 * PADK;
                    sAh[d]     = __byte_perm(w.x, w.y, 0x5410);
                    sAh[d + 1] = __byte_perm(w.z, w.w, 0x5410);
                    sAl[d]     = __byte_perm(w.x, w.y, 0x7632);
                    sAl[d + 1] = __byte_perm(w.z, w.w, 0x7632);
                }
            }
            // ---- build B from packed patch ----
            {
                uint32_t hb[8], lb[8];
                if ((tid & 1) == 0) { BUILD_B_HALF(c9 * 32); }
                else                { BUILD_B_HALF(c9 * 32 + 16); }
                uint32_t* dh = sBh + px_b * PADK + kp_b;
                uint32_t* dl = sBl + px_b * PADK + kp_b;
                *(uint4*)(dh)     = make_uint4(hb[0], hb[1], hb[2], hb[3]);
                *(uint4*)(dh + 4) = make_uint4(hb[4], hb[5], hb[6], hb[7]);
                *(uint4*)(dl)     = make_uint4(lb[0], lb[1], lb[2], lb[3]);
                *(uint4*)(dl + 4) = make_uint4(lb[4], lb[5], lb[6], lb[7]);
            }
            // ---- prefetch weights for next chunk ----
            {
                const int nstep = grp * 9 + c9 + 1;
                if (nstep < nsteps) {
                    const uint32_t* wp = wpA + (size_t)nstep * 32;
#pragma unroll
                    for (int i = 0; i < 4; ++i)
                        wpre[i] = *(const uint4*)(wp + (size_t)(32 * i) * WCin9);
                }
            }
            __syncthreads();   // tiles[buf] ready

            const uint32_t tAh = sb + CSM_TILES + buf * TILEB;
            const uint32_t tAl = tAh + 2 * TILEB;
            const uint32_t tBh = tAh + 4 * TILEB;
            const uint32_t tBl = tAh + 6 * TILEB;

            // ---- compute: 2 k16-steps, ldmatrix fragments, 96 HMMA ----
#pragma unroll
            for (int ks = 0; ks < 2; ++ks) {
                const uint32_t kadd = ks * 32;
                uint32_t ah[2][4], al[2][4];
                LDSM_X4(ah[0][0], ah[0][1], ah[0][2], ah[0][3], tAh + aOff + kadd);
                LDSM_X4(ah[1][0], ah[1][1], ah[1][2], ah[1][3], tAh + aOff + 1280 + kadd);
                LDSM_X4(al[0][0], al[0][1], al[0][2], al[0][3], tAl + aOff + kadd);
                LDSM_X4(al[1][0], al[1][1], al[1][2], al[1][3], tAl + aOff + 1280 + kadd);
#pragma unroll
                for (int nip = 0; nip < 4; ++nip) {
                    uint32_t bh0, bh1, bh2, bh3, bl0, bl1, bl2, bl3;
                    LDSM_X4(bh0, bh1, bh2, bh3, tBh + bOff + nip * 1280 + kadd);
                    LDSM_X4(bl0, bl1, bl2, bl3, tBl + bOff + nip * 1280 + kadd);
                    const int ne = 2 * nip, no = 2 * nip + 1;
                    MMA_F16(acc[0][ne], ah[0], bh0, bh1);
                    MMA_F16(acc[1][ne], ah[1], bh0, bh1);
                    MMA_F16(acc[0][no], ah[0], bh2, bh3);
                    MMA_F16(acc[1][no], ah[1], bh2, bh3);
                    MMA_F16(acc[0][ne], ah[0], bl0, bl1);
                    MMA_F16(acc[1][ne], ah[1], bl0, bl1);
                    MMA_F16(acc[0][no], ah[0], bl2, bl3);
                    MMA_F16(acc[1][no], ah[1], bl2, bl3);
                    MMA_F16(acc[0][ne], al[0], bh0, bh1);
                    MMA_F16(acc[1][ne], al[1], bh0, bh1);
                    MMA_F16(acc[0][no], al[0], bh2, bh3);
                    MMA_F16(acc[1][no], al[1], bh2, bh3);
                }
            }
            buf ^= 1;
        }
    }

    // ---- epilogue: acc -> gmem (bn / relu / accumulate) ----
#pragma unroll
    for (int mi = 0; mi < 2; ++mi) {
#pragma unroll
        for (int rr = 0; rr < 2; ++rr) {
            int co = co0 + mw + mi * 16 + g + rr * 8;
            float s = 1.f, bs = 0.f;
            if (flags & 2) { s = scale[co]; bs = bias[co]; }
            const size_t obase = ((size_t)(b * 512 + co)) * PIX;
#pragma unroll
            for (int ni = 0; ni < 8; ++ni) {
#pragma unroll
                for (int cc = 0; cc < 2; ++cc) {
                    int px = nw + ni * 8 + 2 * tig + cc;
                    size_t oi = obase + (size_t)(tile_h + (px >> 4)) * 96
                              + tile_w + (px & 15);
                    float v = acc[mi][ni][rr * 2 + cc];
                    if (flags & 1) v += outp[oi];
                    v = v * s + bs;
                    if (flags & 4) v = fmaxf(v, 0.f);
                    outp[oi] = v;
                }
            }
        }
    }
}

// ---------------- 1x1 projection (unchanged, proven) -------------------------
__global__ void __launch_bounds__(256)
pw_kernel(const float* __restrict__ in, const float* __restrict__ wgt,
          float* __restrict__ out, int Cin, int CO)
{
    const int px0 = blockIdx.x * 128;
    const int o0  = blockIdx.y * 64;
    const int b   = blockIdx.z;
    __shared__ float sIn[16][128];
    __shared__ float sW[64][17];
    const int tid = threadIdx.x, tx = tid & 15, ty = tid >> 4;
    float acc[4][8];
#pragma unroll
    for (int i = 0; i < 4; ++i)
#pragma unroll
        for (int r = 0; r < 8; ++r) acc[i][r] = 0.f;

    const float* inb = in + (size_t)b * Cin * PIX;
    for (int c0 = 0; c0 < Cin; c0 += 16) {
        __syncthreads();
#pragma unroll
        for (int k = 0; k < 8; ++k) {
            int idx = tid + k*256;
            sIn[idx >> 7][idx & 127] =
                inb[(size_t)(c0 + (idx >> 7)) * PIX + px0 + (idx & 127)];
        }
#pragma unroll
        for (int k = 0; k < 4; ++k) {
            int idx = tid + k*256;
            sW[idx >> 4][idx & 15] =
                wgt[(size_t)(o0 + (idx >> 4)) * Cin + c0 + (idx & 15)];
        }
        __syncthreads();
#pragma unroll
        for (int j = 0; j < 16; ++j) {
            float iv[8];
#pragma unroll
            for (int r = 0; r < 8; ++r) iv[r] = sIn[j][tx + 16*r];
#pragma unroll
            for (int i = 0; i < 4; ++i) {
                float wv = sW[ty*4 + i][j];
#pragma unroll
                for (int r = 0; r < 8; ++r)
                    acc[i][r] = fmaf(wv, iv[r], acc[i][r]);
            }
        }
    }
#pragma unroll
    for (int i = 0; i < 4; ++i)
#pragma unroll
        for (int r = 0; r < 8; ++r)
            out[((size_t)b*CO + o0 + ty*4 + i)*PIX + px0 + tx + 16*r] = acc[i][r];
}

// ---------------- energies (unchanged) ---------------------------------------
__global__ void __launch_bounds__(256)
energyH_kernel(const float* __restrict__ q, const float* __restrict__ k,
               float* __restrict__ att)
{
    const int w = blockIdx.x, b = blockIdx.y;
    __shared__ float sQ[32][96], sK[32][96];
    const int tid = threadIdx.x;
    float acc[36];
#pragma unroll
    for (int i = 0; i < 36; ++i) acc[i] = 0.f;

    for (int c0 = 0; c0 < CQKX; c0 += 32) {
        __syncthreads();
        for (int idx = tid; idx < 32*96; idx += 256) {
            int c = idx / 96, p = idx % 96;
            size_t off = (size_t)(b*CQKX + c0 + c) * PIX + p*96 + w;
            sQ[c][p] = q[off];
            sK[c][p] = k[off];
        }
        __syncthreads();
#pragma unroll
        for (int it = 0; it < 36; ++it) {
            int oi = it*256 + tid;
            int h = oi / 96, gg = oi % 96;
            float s = acc[it];
#pragma unroll
            for (int c = 0; c < 32; ++c) s = fmaf(sQ[c][h], sK[c][gg], s);
            acc[it] = s;
        }
    }
#pragma unroll
    for (int it = 0; it < 36; ++it) {
        int oi = it*256 + tid;
        int h = oi / 96, gg = oi % 96;
        float vv = (gg == h) ? __int_as_float(0xff800000u) : acc[it];
        att[((size_t)((b*96 + h)*96 + w))*192 + gg] = vv;
    }
}

__global__ void __launch_bounds__(256)
energyW_kernel(const float* __restrict__ q, const float* __restrict__ k,
               float* __restrict__ att)
{
    const int h = blockIdx.x, b = blockIdx.y;
    __shared__ float sQ[32][96], sK[32][96];
    const int tid = threadIdx.x;
    float acc[36];
#pragma unroll
    for (int i = 0; i < 36; ++i) acc[i] = 0.f;

    for (int c0 = 0; c0 < CQKX; c0 += 32) {
        __syncthreads();
        for (int idx = tid; idx < 32*96; idx += 256) {
            int c = idx / 96, p = idx % 96;
            size_t off = (size_t)(b*CQKX + c0 + c) * PIX + h*96 + p;
            sQ[c][p] = q[off];
            sK[c][p] = k[off];
        }
        __syncthreads();
#pragma unroll
        for (int it = 0; it < 36; ++it) {
            int oi = it*256 + tid;
            int wc = oi / 96, v2 = oi % 96;
            float s = acc[it];
#pragma unroll
            for (int c = 0; c < 32; ++c) s = fmaf(sQ[c][wc], sK[c][v2], s);
            acc[it] = s;
        }
    }
#pragma unroll
    for (int it = 0; it < 36; ++it) {
        int oi = it*256 + tid;
        int wc = oi / 96, v2 = oi % 96;
        att[((size_t)((b*96 + h)*96 + wc))*192 + 96 + v2] = acc[it];
    }
}

// ---------------- softmax over 192 (unchanged) --------------------------------
__global__ void softmax_kernel(float* __restrict__ att)
{
    const int t = threadIdx.x;
    const size_t base = (size_t)blockIdx.x * 192;
    float v = att[base + t];
    __shared__ float red[6];

    float m = v;
#pragma unroll
    for (int o = 16; o; o >>= 1) m = fmaxf(m, __shfl_xor_sync(0xffffffffu, m, o));
    if ((t & 31) == 0) red[t >> 5] = m;
    __syncthreads();
    m = fmaxf(fmaxf(fmaxf(red[0], red[1]), fmaxf(red[2], red[3])),
              fmaxf(red[4], red[5]));

    float e = expf(v - m);
    float s = e;
#pragma unroll
    for (int o = 16; o; o >>= 1) s += __shfl_xor_sync(0xffffffffu, s, o);
    __syncthreads();
    if ((t & 31) == 0) red[t >> 5] = s;
    __syncthreads();
    s = red[0] + red[1] + red[2] + red[3] + red[4] + red[5];
    att[base + t] = e / s;
}

// ---------------- aggregation (unchanged) -------------------------------------
__global__ void __launch_bounds__(256)
aggH_kernel(const float* __restrict__ v, const float* __restrict__ att,
            const float* __restrict__ feat, const float* __restrict__ gp,
            float* __restrict__ dst)
{
    const int w = blockIdx.x, b = blockIdx.y;
    const int tid = threadIdx.x;
    __shared__ float sA2[96][97];
    __shared__ float sV[16][97];
    const float gm = *gp;

    for (int idx = tid; idx < 96*96; idx += 256) {
        int h = idx / 96, gg = idx % 96;
        sA2[h][gg] = att[((size_t)((b*96 + h)*96 + w))*192 + gg];
    }
    const int clg = tid >> 5;
    const int hq  = tid & 31;

    for (int c0 = 0; c0 < CIX; c0 += 16) {
        __syncthreads();
        for (int idx = tid; idx < 16*96; idx += 256) {
            int cl = idx / 96, gg = idx % 96;
            sV[cl][gg] = v[(size_t)(b*CIX + c0 + cl) * PIX + gg*96 + w];
        }
        __syncthreads();
        float a0[3] = {0.f,0.f,0.f}, a1[3] = {0.f,0.f,0.f};
#pragma unroll 4
        for (int gg = 0; gg < 96; ++gg) {
            float v0 = sV[clg*2][gg], v1 = sV[clg*2+1][gg];
#pragma unroll
            for (int r = 0; r < 3; ++r) {
                float a = sA2[hq + 32*r][gg];
                a0[r] = fmaf(v0, a, a0[r]);
                a1[r] = fmaf(v1, a, a1[r]);
            }
        }
#pragma unroll
        for (int r = 0; r < 3; ++r) {
            int h = hq + 32*r;
            size_t oi0 = ((size_t)(b*CIX + c0 + clg*2    )*96 + h)*96 + w;
            size_t oi1 = ((size_t)(b*CIX + c0 + clg*2 + 1)*96 + h)*96 + w;
            dst[oi0] = feat[oi0] + gm * a0[r];
            dst[oi1] = feat[oi1] + gm * a1[r];
        }
    }
}

__global__ void __launch_bounds__(256)
aggW_kernel(const float* __restrict__ v, const float* __restrict__ att,
            const float* __restrict__ gp, float* __restrict__ dst)
{
    const int h = blockIdx.x, b = blockIdx.y;
    const int tid = threadIdx.x;
    __shared__ float sA2[96][97];
    __shared__ float sV[16][97];
    const float gm = *gp;

    for (int idx = tid; idx < 96*96; idx += 256) {
        int wc = idx / 96, v2 = idx % 96;
        sA2[wc][v2] = att[((size_t)((b*96 + h)*96 + wc))*192 + 96 + v2];
    }
    const int clg = tid >> 5;
    const int wq  = tid & 31;

    for (int c0 = 0; c0 < CIX; c0 += 16) {
        __syncthreads();
        for (int idx = tid; idx < 16*96; idx += 256) {
            int cl = idx / 96, v2 = idx % 96;
            sV[cl][v2] = v[(size_t)(b*CIX + c0 + cl) * PIX + h*96 + v2];
        }
        __syncthreads();
        float a0[3] = {0.f,0.f,0.f}, a1[3] = {0.f,0.f,0.f};
#pragma unroll 4
        for (int v2 = 0; v2 < 96; ++v2) {
            float v0 = sV[clg*2][v2], v1 = sV[clg*2+1][v2];
#pragma unroll
            for (int r = 0; r < 3; ++r) {
                float a = sA2[wq + 32*r][v2];
                a0[r] = fmaf(v0, a, a0[r]);
                a1[r] = fmaf(v1, a, a1[r]);
            }
        }
#pragma unroll
        for (int r = 0; r < 3; ++r) {
            int wc = wq + 32*r;
            size_t oi0 = ((size_t)(b*CIX + c0 + clg*2    )*96 + h)*96 + wc;
            size_t oi1 = ((size_t)(b*CIX + c0 + clg*2 + 1)*96 + h)*96 + wc;
            dst[oi0] += gm * a0[r];
            dst[oi1] += gm * a1[r];
        }
    }
}

// ---------------- final 1x1 (unchanged) ---------------------------------------
__global__ void __launch_bounds__(256)
final_kernel(const float* __restrict__ in, const float* __restrict__ ow,
             const float* __restrict__ ob, float* __restrict__ out)
{
    const int px0 = blockIdx.x * 256;
    const int b   = blockIdx.y;
    const int tid = threadIdx.x;
    __shared__ float sIn[32][256];
    __shared__ float sW[19][32];
    float acc[NCL];
#pragma unroll
    for (int o = 0; o < NCL; ++o) acc[o] = 0.f;

    for (int c0 = 0; c0 < CIX; c0 += 32) {
        __syncthreads();
#pragma unroll
        for (int k = 0; k < 32; ++k)
            sIn[k][tid] = in[(size_t)(b*CIX + c0 + k) * PIX + px0 + tid];
        for (int idx = tid; idx < NCL*32; idx += 256)
            sW[idx >> 5][idx & 31] = ow[(size_t)(idx >> 5) * CIX + c0 + (idx & 31)];
        __syncthreads();
#pragma unroll
        for (int j = 0; j < 32; ++j) {
            float xv = sIn[j][tid];
#pragma unroll
            for (int o = 0; o < NCL; ++o) acc[o] = fmaf(sW[o][j], xv, acc[o]);
        }
    }
#pragma unroll
    for (int o = 0; o < NCL; ++o)
        out[((size_t)(b*NCL + o)) * PIX + px0 + tid] = acc[o] + ob[o];
}

// ---------------- launcher -----------------------------------------------------
extern "C" void kernel_launch(void* const* d_in, const int* in_sizes, int n_in,
                              void* d_out, int out_size)
{
    const float* x       = (const float*)d_in[0];
    const float* conva_w = (const float*)d_in[1];
    const float* bn1_s   = (const float*)d_in[2];
    const float* bn1_b   = (const float*)d_in[3];
    const float* q_w     = (const float*)d_in[4];
    const float* k_w     = (const float*)d_in[5];
    const float* v_w     = (const float*)d_in[6];
    const float* gamma   = (const float*)d_in[7];
    const float* convb_w = (const float*)d_in[8];
    const float* bn2_s   = (const float*)d_in[9];
    const float* bn2_b   = (const float*)d_in[10];
    const float* bott_w  = (const float*)d_in[11];
    const float* bn3_s   = (const float*)d_in[12];
    const float* bn3_b   = (const float*)d_in[13];
    const float* out_w   = (const float*)d_in[14];
    const float* out_b   = (const float*)d_in[15];
    float* out = (float*)d_out;

    float *pA, *pB, *pV, *pQ, *pK, *pAtt;
    uint32_t *pWa, *pWb, *pWt;
    cudaGetSymbolAddress((void**)&pA,   g_A);
    cudaGetSymbolAddress((void**)&pB,   g_Bf);
    cudaGetSymbolAddress((void**)&pV,   g_V);
    cudaGetSymbolAddress((void**)&pQ,   g_Q);
    cudaGetSymbolAddress((void**)&pK,   g_K);
    cudaGetSymbolAddress((void**)&pAtt, g_Att);
    cudaGetSymbolAddress((void**)&pWa,  g_Wa);
    cudaGetSymbolAddress((void**)&pWb,  g_Wb);
    cudaGetSymbolAddress((void**)&pWt,  g_Wt);

    cudaFuncSetAttribute(conv_tc_kernel,
                         cudaFuncAttributeMaxDynamicSharedMemorySize, CSM_TOTAL);

    // pre-split weights (hi/lo f16 packed)
    const int nWa = CIX * CINX * 9;
    const int nWb = CIX * CIX * 9;
    const int nWt = CIX * (CINX + CIX) * 9;
    prep_w_kernel<<<(nWa + 255)/256, 256>>>(conva_w, pWa, nWa);
    prep_w_kernel<<<(nWb + 255)/256, 256>>>(convb_w, pWb, nWb);
    prep_w_kernel<<<(nWt + 255)/256, 256>>>(bott_w,  pWt, nWt);

    dim3 cgrid(6, 12, BB * (CIX/128));   // (6,12,8), 256 threads, 2 CTA/SM

    // conva + bn1 + relu -> A
    conv_tc_kernel<<<cgrid, 256, CSM_TOTAL>>>(x, pWa, bn1_s, bn1_b, pA,
                                              CINX, CINX*9, 0, 2|4);

    // 2 recurrences of criss-cross attention (fp32, proven)
    for (int r = 0; r < 2; ++r) {
        const float* feat = r ? pB : pA;
        float*       dst  = r ? pA : pB;
        pw_kernel<<<dim3(72, 1, BB), 256>>>(feat, q_w, pQ, CIX, CQKX);
        pw_kernel<<<dim3(72, 1, BB), 256>>>(feat, k_w, pK, CIX, CQKX);
        pw_kernel<<<dim3(72, 8, BB), 256>>>(feat, v_w, pV, CIX, CIX);
        energyH_kernel<<<dim3(96, BB), 256>>>(pQ, pK, pAtt);
        energyW_kernel<<<dim3(96, BB), 256>>>(pQ, pK, pAtt);
        softmax_kernel<<<BB*PIX, 192>>>(pAtt);
        aggH_kernel<<<dim3(96, BB), 256>>>(pV, pAtt, feat, gamma, dst);
        aggW_kernel<<<dim3(96, BB), 256>>>(pV, pAtt, gamma, dst);
    }

    // convb + bn2 + relu : A -> B
    conv_tc_kernel<<<cgrid, 256, CSM_TOTAL>>>(pA, pWb, bn2_s, bn2_b, pB,
                                              CIX, CIX*9, 0, 2|4);

    // bottleneck conv over virtual concat [x (2048ch), B (512ch)] -> V, bn3
    conv_tc_kernel<<<cgrid, 256, CSM_TOTAL>>>(x,  pWt, nullptr, nullptr, pV,
                                              CINX, (CINX+CIX)*9, 0, 0);
    conv_tc_kernel<<<cgrid, 256, CSM_TOTAL>>>(pB, pWt, bn3_s, bn3_b, pV,
                                              CIX, (CINX+CIX)*9, CINX*9, 1|2);

    // final 1x1 -> d_out
    final_kernel<<<dim3(PIX/256, BB), 256>>>(pV, out_w, out_b, out);
}